// round 12
// baseline (speedup 1.0000x reference)
#include <cuda_runtime.h>
#include <cuda_bf16.h>
#include <mma.h>
#include <math.h>
#include <stdint.h>

#define NLEV 16
#define TBL (1u << 19)
#define NMAX (1 << 20)

struct LevelP {
    float scale[NLEV];
    uint32_t res[NLEV];
    uint32_t dense_mask;
};

// Planar float4 scratch for h[16] per point: 4 planes x 16 MB = 64 MB.
__device__ float4 g_h0[NMAX];
__device__ float4 g_h1[NMAX];
__device__ float4 g_h2[NMAX];
__device__ float4 g_h3[NMAX];

// ---------------- grid encode for one point (enc stays in regs) -------------
__device__ __forceinline__ void grid_encode_pt(float px, float py, float pz,
                                               const float* __restrict__ table,
                                               const LevelP& lp, float* enc)
{
    #pragma unroll
    for (int l = 0; l < NLEV; l++) {
        const float s = lp.scale[l];
        const uint32_t res = lp.res[l];
        const bool dense = (lp.dense_mask >> l) & 1u;

        float posx = __fadd_rn(__fmul_rn(px, s), 0.5f);
        float posy = __fadd_rn(__fmul_rn(py, s), 0.5f);
        float posz = __fadd_rn(__fmul_rn(pz, s), 0.5f);
        float gxf = floorf(posx), gyf = floorf(posy), gzf = floorf(posz);
        float fx = posx - gxf, fy = posy - gyf, fz = posz - gzf;
        uint32_t X = (uint32_t)gxf, Y = (uint32_t)gyf, Z = (uint32_t)gzf;

        const float2* tab = (const float2*)table + (size_t)l * TBL;

        uint32_t hy0 = Y * 2654435761u;
        uint32_t hy1 = (Y + 1u) * 2654435761u;
        uint32_t hz0 = Z * 805459861u;
        uint32_t hz1 = (Z + 1u) * 805459861u;
        uint32_t dy0 = Y * res,        dy1 = (Y + 1u) * res;
        uint32_t dz0 = Z * res * res,  dz1 = (Z + 1u) * res * res;

        float wx1 = fx, wx0 = 1.0f - fx;
        float wy1 = fy, wy0 = 1.0f - fy;
        float wz1 = fz, wz0 = 1.0f - fz;

        float e0 = 0.0f, e1 = 0.0f;
        #pragma unroll
        for (int c = 0; c < 8; c++) {
            const uint32_t bi = (c >> 2) & 1, bj = (c >> 1) & 1, bk = c & 1;
            uint32_t cx = X + bi;
            uint32_t idx;
            if (dense) {
                idx = cx + (bj ? dy1 : dy0) + (bk ? dz1 : dz0);
            } else {
                idx = (cx ^ (bj ? hy1 : hy0) ^ (bk ? hz1 : hz0)) & (TBL - 1u);
            }
            float w = (bi ? wx1 : wx0) * (bj ? wy1 : wy0) * (bk ? wz1 : wz0);
            float2 f = __ldg(tab + idx);
            e0 = fmaf(f.x, w, e0);
            e1 = fmaf(f.y, w, e1);
        }
        enc[2 * l + 0] = e0;
        enc[2 * l + 1] = e1;
    }
}

// ============================ Kernel 1: dual-point encode ===================
__global__ __launch_bounds__(128, 2)
void ngp_encode_kernel(const float* __restrict__ gx,
                       const float* __restrict__ table,
                       const float* __restrict__ w1,
                       const float* __restrict__ w2,
                       const float* __restrict__ wa1,
                       const float* __restrict__ wa2,
                       const float* __restrict__ wu1,
                       const float* __restrict__ wu2,
                       float* __restrict__ out,
                       int N, LevelP lp)
{
    __shared__ __align__(16) float s_w1T[64 * 32];
    __shared__ __align__(16) float s_w2[64 * 16];
    __shared__ __align__(16) float s_wa1T[32 * 16];
    __shared__ __align__(16) float s_wa2[32];
    __shared__ __align__(16) float s_wuf[16];

    const int tid = threadIdx.x;
    for (int t = tid; t < 64 * 32; t += 128) {
        int j = t >> 5, i = t & 31;
        s_w1T[t] = w1[i * 64 + j];
    }
    for (int t = tid; t < 64 * 16; t += 128) s_w2[t] = w2[t];
    for (int t = tid; t < 32 * 16; t += 128) {
        int j = t >> 4, i = t & 15;
        s_wa1T[t] = wa1[i * 32 + j];
    }
    if (tid < 32) s_wa2[tid] = wa2[tid];
    if (tid < 16) {
        float acc = 0.0f;
        for (int j = 0; j < 32; j++) acc = fmaf(wu1[tid * 32 + j], wu2[j], acc);
        s_wuf[tid] = acc;
    }
    __syncthreads();

    const int p0 = blockIdx.x * 256 + tid;
    if (p0 >= N) return;
    int p1 = p0 + 128;
    const bool has1 = (p1 < N);
    if (!has1) p1 = p0;

    float px0 = __fmul_rn(__fadd_rn(gx[3 * p0 + 0], 1.0f), 0.5f);
    float py0 = __fmul_rn(__fadd_rn(gx[3 * p0 + 1], 1.0f), 0.5f);
    float pz0 = __fmul_rn(__fadd_rn(gx[3 * p0 + 2], 1.0f), 0.5f);
    float px1 = __fmul_rn(__fadd_rn(gx[3 * p1 + 0], 1.0f), 0.5f);
    float py1 = __fmul_rn(__fadd_rn(gx[3 * p1 + 1], 1.0f), 0.5f);
    float pz1 = __fmul_rn(__fadd_rn(gx[3 * p1 + 2], 1.0f), 0.5f);

    float enc0[32], enc1[32];
    grid_encode_pt(px0, py0, pz0, table, lp, enc0);
    grid_encode_pt(px1, py1, pz1, table, lp, enc1);

    float h0[16], h1[16];
    #pragma unroll
    for (int k = 0; k < 16; k++) { h0[k] = 0.0f; h1[k] = 0.0f; }
    #pragma unroll 2
    for (int j = 0; j < 64; j++) {
        const float4* wr = (const float4*)&s_w1T[j * 32];
        float a0 = 0.0f, a1 = 0.0f;
        #pragma unroll
        for (int q = 0; q < 8; q++) {
            float4 w4 = wr[q];
            a0 = fmaf(enc0[4 * q + 0], w4.x, a0);
            a0 = fmaf(enc0[4 * q + 1], w4.y, a0);
            a0 = fmaf(enc0[4 * q + 2], w4.z, a0);
            a0 = fmaf(enc0[4 * q + 3], w4.w, a0);
            a1 = fmaf(enc1[4 * q + 0], w4.x, a1);
            a1 = fmaf(enc1[4 * q + 1], w4.y, a1);
            a1 = fmaf(enc1[4 * q + 2], w4.z, a1);
            a1 = fmaf(enc1[4 * q + 3], w4.w, a1);
        }
        float t0 = fmaxf(a0, 0.0f), t1 = fmaxf(a1, 0.0f);
        const float4* w2r = (const float4*)&s_w2[j * 16];
        #pragma unroll
        for (int q = 0; q < 4; q++) {
            float4 w4 = w2r[q];
            h0[4 * q + 0] = fmaf(t0, w4.x, h0[4 * q + 0]);
            h0[4 * q + 1] = fmaf(t0, w4.y, h0[4 * q + 1]);
            h0[4 * q + 2] = fmaf(t0, w4.z, h0[4 * q + 2]);
            h0[4 * q + 3] = fmaf(t0, w4.w, h0[4 * q + 3]);
            h1[4 * q + 0] = fmaf(t1, w4.x, h1[4 * q + 0]);
            h1[4 * q + 1] = fmaf(t1, w4.y, h1[4 * q + 1]);
            h1[4 * q + 2] = fmaf(t1, w4.z, h1[4 * q + 2]);
            h1[4 * q + 3] = fmaf(t1, w4.w, h1[4 * q + 3]);
        }
    }

    float sacc0 = 0.0f, sacc1 = 0.0f;
    #pragma unroll 4
    for (int j = 0; j < 32; j++) {
        const float4* wa = (const float4*)&s_wa1T[j * 16];
        float a0 = 0.0f, a1 = 0.0f;
        #pragma unroll
        for (int q = 0; q < 4; q++) {
            float4 w4 = wa[q];
            a0 = fmaf(h0[4 * q + 0], w4.x, a0);
            a0 = fmaf(h0[4 * q + 1], w4.y, a0);
            a0 = fmaf(h0[4 * q + 2], w4.z, a0);
            a0 = fmaf(h0[4 * q + 3], w4.w, a0);
            a1 = fmaf(h1[4 * q + 0], w4.x, a1);
            a1 = fmaf(h1[4 * q + 1], w4.y, a1);
            a1 = fmaf(h1[4 * q + 2], w4.z, a1);
            a1 = fmaf(h1[4 * q + 3], w4.w, a1);
        }
        float w = s_wa2[j];
        sacc0 = fmaf(fmaxf(a0, 0.0f), w, sacc0);
        sacc1 = fmaf(fmaxf(a1, 0.0f), w, sacc1);
    }

    float uacc0 = 0.0f, uacc1 = 0.0f;
    #pragma unroll
    for (int q = 0; q < 4; q++) {
        float4 w4 = ((const float4*)s_wuf)[q];
        uacc0 = fmaf(h0[4 * q + 0], w4.x, uacc0);
        uacc0 = fmaf(h0[4 * q + 1], w4.y, uacc0);
        uacc0 = fmaf(h0[4 * q + 2], w4.z, uacc0);
        uacc0 = fmaf(h0[4 * q + 3], w4.w, uacc0);
        uacc1 = fmaf(h1[4 * q + 0], w4.x, uacc1);
        uacc1 = fmaf(h1[4 * q + 1], w4.y, uacc1);
        uacc1 = fmaf(h1[4 * q + 2], w4.z, uacc1);
        uacc1 = fmaf(h1[4 * q + 3], w4.w, uacc1);
    }

    out[p0] = __expf(sacc0);
    out[4 * N + p0] = __expf(uacc0);
    g_h0[p0] = make_float4(h0[0],  h0[1],  h0[2],  h0[3]);
    g_h1[p0] = make_float4(h0[4],  h0[5],  h0[6],  h0[7]);
    g_h2[p0] = make_float4(h0[8],  h0[9],  h0[10], h0[11]);
    g_h3[p0] = make_float4(h0[12], h0[13], h0[14], h0[15]);
    if (has1) {
        out[p1] = __expf(sacc1);
        out[4 * N + p1] = __expf(uacc1);
        g_h0[p1] = make_float4(h1[0],  h1[1],  h1[2],  h1[3]);
        g_h1[p1] = make_float4(h1[4],  h1[5],  h1[6],  h1[7]);
        g_h2[p1] = make_float4(h1[8],  h1[9],  h1[10], h1[11]);
        g_h3[p1] = make_float4(h1[12], h1[13], h1[14], h1[15]);
    }
}

// ============================ Kernel 2: wmma (HMMA) render ==================
// Per 128-point block: A0=[sh|h] (K=32) -> z1=relu(A0@W1) (64)
//   -> z2=relu(z1@W2) (64) -> rgb=sigmoid(z2@W3[:, :3])
// Split-bf16 (Markidis): x = hi + lo; D = hi*hi + hi*lo + lo*hi in fp32 acc.
// W matrices are [K][N] row-major already (fan_in x fan_out).

#define LDA 72           // bf16/f32 staging ldm (multiple of 8, low-conflict)
#define LDB3 24          // layer-3 B ldm (16 cols used)
// dynamic smem offsets (bytes)
#define R_AH   0         // [128][72] bf16
#define R_AL   18432     // [128][72] bf16
#define R_C    36864     // [128][72] f32
#define R_B1H  73728     // [32][72]  bf16
#define R_B1L  78336
#define R_B2H  82944     // [64][72]  bf16
#define R_B2L  92160
#define R_B3H  101376    // [64][24]  bf16
#define R_B3L  104448
#define R_SMEM 107520

using namespace nvcuda;

__device__ __forceinline__ void split_w(float v, __nv_bfloat16& hi, __nv_bfloat16& lo) {
    hi = __float2bfloat16(v);
    lo = __float2bfloat16(v - __bfloat162float(hi));
}

template <int KTILES, int NTILES, int BLDM>
__device__ __forceinline__ void wmma_layer(const __nv_bfloat16* sAH,
                                           const __nv_bfloat16* sAL,
                                           const __nv_bfloat16* sBH,
                                           const __nv_bfloat16* sBL,
                                           float* sC, int wid)
{
    const int m0 = wid * 32;
    #pragma unroll
    for (int nt = 0; nt < NTILES; nt++) {
        wmma::fragment<wmma::matrix_b, 16, 16, 16, __nv_bfloat16, wmma::row_major> bh[KTILES], bl[KTILES];
        #pragma unroll
        for (int k = 0; k < KTILES; k++) {
            wmma::load_matrix_sync(bh[k], sBH + k * 16 * BLDM + nt * 16, BLDM);
            wmma::load_matrix_sync(bl[k], sBL + k * 16 * BLDM + nt * 16, BLDM);
        }
        #pragma unroll
        for (int ms = 0; ms < 2; ms++) {
            const int m = m0 + ms * 16;
            wmma::fragment<wmma::accumulator, 16, 16, 16, float> acc;
            wmma::fill_fragment(acc, 0.0f);
            #pragma unroll
            for (int k = 0; k < KTILES; k++) {
                wmma::fragment<wmma::matrix_a, 16, 16, 16, __nv_bfloat16, wmma::row_major> ah, al;
                wmma::load_matrix_sync(ah, sAH + m * LDA + k * 16, LDA);
                wmma::load_matrix_sync(al, sAL + m * LDA + k * 16, LDA);
                wmma::mma_sync(acc, ah, bh[k], acc);
                wmma::mma_sync(acc, ah, bl[k], acc);
                wmma::mma_sync(acc, al, bh[k], acc);
            }
            wmma::store_matrix_sync(sC + m * LDA + nt * 16, acc, LDA, wmma::mem_row_major);
        }
    }
}

__global__ __launch_bounds__(128)
void ngp_render_wmma(const float* __restrict__ gd,
                     const float* __restrict__ wr1,
                     const float* __restrict__ wr2,
                     const float* __restrict__ wr3,
                     float* __restrict__ out,
                     int N)
{
    extern __shared__ char dsm[];
    __nv_bfloat16* sAH  = (__nv_bfloat16*)(dsm + R_AH);
    __nv_bfloat16* sAL  = (__nv_bfloat16*)(dsm + R_AL);
    float*         sC   = (float*)(dsm + R_C);
    __nv_bfloat16* sB1H = (__nv_bfloat16*)(dsm + R_B1H);
    __nv_bfloat16* sB1L = (__nv_bfloat16*)(dsm + R_B1L);
    __nv_bfloat16* sB2H = (__nv_bfloat16*)(dsm + R_B2H);
    __nv_bfloat16* sB2L = (__nv_bfloat16*)(dsm + R_B2L);
    __nv_bfloat16* sB3H = (__nv_bfloat16*)(dsm + R_B3H);
    __nv_bfloat16* sB3L = (__nv_bfloat16*)(dsm + R_B3L);

    const int tid = threadIdx.x;
    const int wid = tid >> 5;

    // -------- stage split-bf16 weights ([K][N] row-major, padded ldm) --------
    for (int t = tid; t < 32 * 64; t += 128) {
        int k = t >> 6, n = t & 63;
        __nv_bfloat16 hi, lo;
        split_w(wr1[k * 64 + n], hi, lo);
        sB1H[k * LDA + n] = hi;
        sB1L[k * LDA + n] = lo;
    }
    for (int t = tid; t < 64 * 64; t += 128) {
        int k = t >> 6, n = t & 63;
        __nv_bfloat16 hi, lo;
        split_w(wr2[k * 64 + n], hi, lo);
        sB2H[k * LDA + n] = hi;
        sB2L[k * LDA + n] = lo;
    }
    for (int t = tid; t < 64 * 16; t += 128) {
        int k = t >> 4, n = t & 15;
        float w = (n < 3) ? wr3[k * 3 + n] : 0.0f;
        __nv_bfloat16 hi, lo;
        split_w(w, hi, lo);
        sB3H[k * LDB3 + n] = hi;
        sB3L[k * LDB3 + n] = lo;
    }

    // -------- build A0 = [sh | h] (row = tid, K=32) ---------------------------
    const int p = blockIdx.x * 128 + tid;
    const int pc = (p < N) ? p : (N - 1);
    float a0[32];
    {
        float4 v;
        v = g_h0[pc]; a0[16]=v.x; a0[17]=v.y; a0[18]=v.z; a0[19]=v.w;
        v = g_h1[pc]; a0[20]=v.x; a0[21]=v.y; a0[22]=v.z; a0[23]=v.w;
        v = g_h2[pc]; a0[24]=v.x; a0[25]=v.y; a0[26]=v.z; a0[27]=v.w;
        v = g_h3[pc]; a0[28]=v.x; a0[29]=v.y; a0[30]=v.z; a0[31]=v.w;
        float vx = __fadd_rn(__fadd_rn(gd[3 * pc + 0], 1.0f), -1.0f);
        float vy = __fadd_rn(__fadd_rn(gd[3 * pc + 1], 1.0f), -1.0f);
        float vz = __fadd_rn(__fadd_rn(gd[3 * pc + 2], 1.0f), -1.0f);
        float x2 = vx * vx, y2 = vy * vy, z2 = vz * vz;
        float xy = vx * vy, yz = vy * vz, xz = vx * vz;
        a0[0]  = 0.28209479177387814f;
        a0[1]  = -0.48860251190291987f * vy;
        a0[2]  = 0.48860251190291987f * vz;
        a0[3]  = -0.48860251190291987f * vx;
        a0[4]  = 1.0925484305920792f * xy;
        a0[5]  = -1.0925484305920792f * yz;
        a0[6]  = 0.94617469575756f * z2 - 0.31539156525252f;
        a0[7]  = -1.0925484305920792f * xz;
        a0[8]  = 0.5462742152960396f * (x2 - y2);
        a0[9]  = 0.5900435899266435f * vy * (-3.0f * x2 + y2);
        a0[10] = 2.890611442640554f * xy * vz;
        a0[11] = 0.4570457994644657f * vy * (1.0f - 5.0f * z2);
        a0[12] = 0.3731763325901154f * vz * (5.0f * z2 - 3.0f);
        a0[13] = 0.4570457994644657f * vx * (1.0f - 5.0f * z2);
        a0[14] = 1.445305721320277f * vz * (x2 - y2);
        a0[15] = 0.5900435899266435f * vx * (-x2 + 3.0f * y2);
    }
    #pragma unroll
    for (int k = 0; k < 32; k++) {
        __nv_bfloat16 hi, lo;
        split_w(a0[k], hi, lo);
        sAH[tid * LDA + k] = hi;
        sAL[tid * LDA + k] = lo;
    }
    __syncthreads();

    // -------- layer 1: [128x32] @ W1[32x64] -----------------------------------
    wmma_layer<2, 4, LDA>(sAH, sAL, sB1H, sB1L, sC, wid);
    __syncthreads();
    #pragma unroll
    for (int j = 0; j < 64; j += 4) {
        float4 v = *(const float4*)&sC[tid * LDA + j];
        v.x = fmaxf(v.x, 0.0f); v.y = fmaxf(v.y, 0.0f);
        v.z = fmaxf(v.z, 0.0f); v.w = fmaxf(v.w, 0.0f);
        __nv_bfloat16 h, l;
        split_w(v.x, h, l); sAH[tid * LDA + j + 0] = h; sAL[tid * LDA + j + 0] = l;
        split_w(v.y, h, l); sAH[tid * LDA + j + 1] = h; sAL[tid * LDA + j + 1] = l;
        split_w(v.z, h, l); sAH[tid * LDA + j + 2] = h; sAL[tid * LDA + j + 2] = l;
        split_w(v.w, h, l); sAH[tid * LDA + j + 3] = h; sAL[tid * LDA + j + 3] = l;
    }
    __syncthreads();

    // -------- layer 2: [128x64] @ W2[64x64] -----------------------------------
    wmma_layer<4, 4, LDA>(sAH, sAL, sB2H, sB2L, sC, wid);
    __syncthreads();
    #pragma unroll
    for (int j = 0; j < 64; j += 4) {
        float4 v = *(const float4*)&sC[tid * LDA + j];
        v.x = fmaxf(v.x, 0.0f); v.y = fmaxf(v.y, 0.0f);
        v.z = fmaxf(v.z, 0.0f); v.w = fmaxf(v.w, 0.0f);
        __nv_bfloat16 h, l;
        split_w(v.x, h, l); sAH[tid * LDA + j + 0] = h; sAL[tid * LDA + j + 0] = l;
        split_w(v.y, h, l); sAH[tid * LDA + j + 1] = h; sAL[tid * LDA + j + 1] = l;
        split_w(v.z, h, l); sAH[tid * LDA + j + 2] = h; sAL[tid * LDA + j + 2] = l;
        split_w(v.w, h, l); sAH[tid * LDA + j + 3] = h; sAL[tid * LDA + j + 3] = l;
    }
    __syncthreads();

    // -------- layer 3: [128x64] @ W3[64x16(pad)] ------------------------------
    wmma_layer<4, 1, LDB3>(sAH, sAL, sB3H, sB3L, sC, wid);
    __syncthreads();

    if (p < N) {
        float r0 = sC[tid * LDA + 0];
        float r1 = sC[tid * LDA + 1];
        float r2 = sC[tid * LDA + 2];
        out[N + 3 * p + 0] = __fdividef(1.0f, 1.0f + __expf(-r0));
        out[N + 3 * p + 1] = __fdividef(1.0f, 1.0f + __expf(-r1));
        out[N + 3 * p + 2] = __fdividef(1.0f, 1.0f + __expf(-r2));
    }
}

extern "C" void kernel_launch(void* const* d_in, const int* in_sizes, int n_in,
                              void* d_out, int out_size) {
    const float* x     = (const float*)d_in[0];
    const float* d     = (const float*)d_in[1];
    const float* table = (const float*)d_in[2];
    const float* w1    = (const float*)d_in[3];
    const float* w2    = (const float*)d_in[4];
    const float* wa1   = (const float*)d_in[5];
    const float* wa2   = (const float*)d_in[6];
    const float* wu1   = (const float*)d_in[7];
    const float* wu2   = (const float*)d_in[8];
    const float* wr1   = (const float*)d_in[9];
    const float* wr2   = (const float*)d_in[10];
    const float* wr3   = (const float*)d_in[11];
    float* out = (float*)d_out;

    int N = in_sizes[0] / 3;

    LevelP lp;
    double Bv = exp(log(2048.0 / 16.0) / 15.0);
    uint32_t mask = 0;
    for (int l = 0; l < NLEV; l++) {
        double s = 16.0 * pow(Bv, (double)l) - 1.0;
        lp.scale[l] = (float)s;
        long long r = (long long)ceil(s) + 1;
        lp.res[l] = (uint32_t)r;
        if (r * r * r <= (long long)TBL) mask |= (1u << l);
    }
    lp.dense_mask = mask;

    static int smem_set = 0;
    if (!smem_set) {
        cudaFuncSetAttribute(ngp_render_wmma,
                             cudaFuncAttributeMaxDynamicSharedMemorySize,
                             R_SMEM);
        smem_set = 1;
    }

    int eblocks = (N + 255) / 256;
    ngp_encode_kernel<<<eblocks, 128>>>(x, table, w1, w2, wa1, wa2,
                                        wu1, wu2, out, N, lp);
    int rblocks = (N + 127) / 128;
    ngp_render_wmma<<<rblocks, 128, R_SMEM>>>(d, wr1, wr2, wr3, out, N);
}

// round 13
// speedup vs baseline: 1.0579x; 1.0579x over previous
#include <cuda_runtime.h>
#include <cuda_bf16.h>
#include <mma.h>
#include <math.h>
#include <stdint.h>

#define NLEV 16
#define TBL (1u << 19)
#define NMAX (1 << 20)

struct LevelP {
    float scale[NLEV];
    uint32_t res[NLEV];
    uint32_t dense_mask;
};

// Planar float4 scratch for h[16] per point: 4 planes x 16 MB = 64 MB.
__device__ float4 g_h0[NMAX];
__device__ float4 g_h1[NMAX];
__device__ float4 g_h2[NMAX];
__device__ float4 g_h3[NMAX];

// ---------------- grid encode for one point (enc stays in regs) -------------
__device__ __forceinline__ void grid_encode_pt(float px, float py, float pz,
                                               const float* __restrict__ table,
                                               const LevelP& lp, float* enc)
{
    #pragma unroll
    for (int l = 0; l < NLEV; l++) {
        const float s = lp.scale[l];
        const uint32_t res = lp.res[l];
        const bool dense = (lp.dense_mask >> l) & 1u;

        float posx = __fadd_rn(__fmul_rn(px, s), 0.5f);
        float posy = __fadd_rn(__fmul_rn(py, s), 0.5f);
        float posz = __fadd_rn(__fmul_rn(pz, s), 0.5f);
        float gxf = floorf(posx), gyf = floorf(posy), gzf = floorf(posz);
        float fx = posx - gxf, fy = posy - gyf, fz = posz - gzf;
        uint32_t X = (uint32_t)gxf, Y = (uint32_t)gyf, Z = (uint32_t)gzf;

        const float2* tab = (const float2*)table + (size_t)l * TBL;

        uint32_t hy0 = Y * 2654435761u;
        uint32_t hy1 = (Y + 1u) * 2654435761u;
        uint32_t hz0 = Z * 805459861u;
        uint32_t hz1 = (Z + 1u) * 805459861u;
        uint32_t dy0 = Y * res,        dy1 = (Y + 1u) * res;
        uint32_t dz0 = Z * res * res,  dz1 = (Z + 1u) * res * res;

        float wx1 = fx, wx0 = 1.0f - fx;
        float wy1 = fy, wy0 = 1.0f - fy;
        float wz1 = fz, wz0 = 1.0f - fz;

        float e0 = 0.0f, e1 = 0.0f;
        #pragma unroll
        for (int c = 0; c < 8; c++) {
            const uint32_t bi = (c >> 2) & 1, bj = (c >> 1) & 1, bk = c & 1;
            uint32_t cx = X + bi;
            uint32_t idx;
            if (dense) {
                idx = cx + (bj ? dy1 : dy0) + (bk ? dz1 : dz0);
            } else {
                idx = (cx ^ (bj ? hy1 : hy0) ^ (bk ? hz1 : hz0)) & (TBL - 1u);
            }
            float w = (bi ? wx1 : wx0) * (bj ? wy1 : wy0) * (bk ? wz1 : wz0);
            float2 f = __ldg(tab + idx);
            e0 = fmaf(f.x, w, e0);
            e1 = fmaf(f.y, w, e1);
        }
        enc[2 * l + 0] = e0;
        enc[2 * l + 1] = e1;
    }
}

// ============================ Kernel 1: dual-point encode ===================
__global__ __launch_bounds__(128, 2)
void ngp_encode_kernel(const float* __restrict__ gx,
                       const float* __restrict__ table,
                       const float* __restrict__ w1,
                       const float* __restrict__ w2,
                       const float* __restrict__ wa1,
                       const float* __restrict__ wa2,
                       const float* __restrict__ wu1,
                       const float* __restrict__ wu2,
                       float* __restrict__ out,
                       int N, LevelP lp)
{
    __shared__ __align__(16) float s_w1T[64 * 32];
    __shared__ __align__(16) float s_w2[64 * 16];
    __shared__ __align__(16) float s_wa1T[32 * 16];
    __shared__ __align__(16) float s_wa2[32];
    __shared__ __align__(16) float s_wuf[16];

    const int tid = threadIdx.x;
    for (int t = tid; t < 64 * 32; t += 128) {
        int j = t >> 5, i = t & 31;
        s_w1T[t] = w1[i * 64 + j];
    }
    for (int t = tid; t < 64 * 16; t += 128) s_w2[t] = w2[t];
    for (int t = tid; t < 32 * 16; t += 128) {
        int j = t >> 4, i = t & 15;
        s_wa1T[t] = wa1[i * 32 + j];
    }
    if (tid < 32) s_wa2[tid] = wa2[tid];
    if (tid < 16) {
        float acc = 0.0f;
        for (int j = 0; j < 32; j++) acc = fmaf(wu1[tid * 32 + j], wu2[j], acc);
        s_wuf[tid] = acc;
    }
    __syncthreads();

    const int p0 = blockIdx.x * 256 + tid;
    if (p0 >= N) return;
    int p1 = p0 + 128;
    const bool has1 = (p1 < N);
    if (!has1) p1 = p0;

    float px0 = __fmul_rn(__fadd_rn(gx[3 * p0 + 0], 1.0f), 0.5f);
    float py0 = __fmul_rn(__fadd_rn(gx[3 * p0 + 1], 1.0f), 0.5f);
    float pz0 = __fmul_rn(__fadd_rn(gx[3 * p0 + 2], 1.0f), 0.5f);
    float px1 = __fmul_rn(__fadd_rn(gx[3 * p1 + 0], 1.0f), 0.5f);
    float py1 = __fmul_rn(__fadd_rn(gx[3 * p1 + 1], 1.0f), 0.5f);
    float pz1 = __fmul_rn(__fadd_rn(gx[3 * p1 + 2], 1.0f), 0.5f);

    float enc0[32], enc1[32];
    grid_encode_pt(px0, py0, pz0, table, lp, enc0);
    grid_encode_pt(px1, py1, pz1, table, lp, enc1);

    float h0[16], h1[16];
    #pragma unroll
    for (int k = 0; k < 16; k++) { h0[k] = 0.0f; h1[k] = 0.0f; }
    #pragma unroll 2
    for (int j = 0; j < 64; j++) {
        const float4* wr = (const float4*)&s_w1T[j * 32];
        float a0 = 0.0f, a1 = 0.0f;
        #pragma unroll
        for (int q = 0; q < 8; q++) {
            float4 w4 = wr[q];
            a0 = fmaf(enc0[4 * q + 0], w4.x, a0);
            a0 = fmaf(enc0[4 * q + 1], w4.y, a0);
            a0 = fmaf(enc0[4 * q + 2], w4.z, a0);
            a0 = fmaf(enc0[4 * q + 3], w4.w, a0);
            a1 = fmaf(enc1[4 * q + 0], w4.x, a1);
            a1 = fmaf(enc1[4 * q + 1], w4.y, a1);
            a1 = fmaf(enc1[4 * q + 2], w4.z, a1);
            a1 = fmaf(enc1[4 * q + 3], w4.w, a1);
        }
        float t0 = fmaxf(a0, 0.0f), t1 = fmaxf(a1, 0.0f);
        const float4* w2r = (const float4*)&s_w2[j * 16];
        #pragma unroll
        for (int q = 0; q < 4; q++) {
            float4 w4 = w2r[q];
            h0[4 * q + 0] = fmaf(t0, w4.x, h0[4 * q + 0]);
            h0[4 * q + 1] = fmaf(t0, w4.y, h0[4 * q + 1]);
            h0[4 * q + 2] = fmaf(t0, w4.z, h0[4 * q + 2]);
            h0[4 * q + 3] = fmaf(t0, w4.w, h0[4 * q + 3]);
            h1[4 * q + 0] = fmaf(t1, w4.x, h1[4 * q + 0]);
            h1[4 * q + 1] = fmaf(t1, w4.y, h1[4 * q + 1]);
            h1[4 * q + 2] = fmaf(t1, w4.z, h1[4 * q + 2]);
            h1[4 * q + 3] = fmaf(t1, w4.w, h1[4 * q + 3]);
        }
    }

    float sacc0 = 0.0f, sacc1 = 0.0f;
    #pragma unroll 4
    for (int j = 0; j < 32; j++) {
        const float4* wa = (const float4*)&s_wa1T[j * 16];
        float a0 = 0.0f, a1 = 0.0f;
        #pragma unroll
        for (int q = 0; q < 4; q++) {
            float4 w4 = wa[q];
            a0 = fmaf(h0[4 * q + 0], w4.x, a0);
            a0 = fmaf(h0[4 * q + 1], w4.y, a0);
            a0 = fmaf(h0[4 * q + 2], w4.z, a0);
            a0 = fmaf(h0[4 * q + 3], w4.w, a0);
            a1 = fmaf(h1[4 * q + 0], w4.x, a1);
            a1 = fmaf(h1[4 * q + 1], w4.y, a1);
            a1 = fmaf(h1[4 * q + 2], w4.z, a1);
            a1 = fmaf(h1[4 * q + 3], w4.w, a1);
        }
        float w = s_wa2[j];
        sacc0 = fmaf(fmaxf(a0, 0.0f), w, sacc0);
        sacc1 = fmaf(fmaxf(a1, 0.0f), w, sacc1);
    }

    float uacc0 = 0.0f, uacc1 = 0.0f;
    #pragma unroll
    for (int q = 0; q < 4; q++) {
        float4 w4 = ((const float4*)s_wuf)[q];
        uacc0 = fmaf(h0[4 * q + 0], w4.x, uacc0);
        uacc0 = fmaf(h0[4 * q + 1], w4.y, uacc0);
        uacc0 = fmaf(h0[4 * q + 2], w4.z, uacc0);
        uacc0 = fmaf(h0[4 * q + 3], w4.w, uacc0);
        uacc1 = fmaf(h1[4 * q + 0], w4.x, uacc1);
        uacc1 = fmaf(h1[4 * q + 1], w4.y, uacc1);
        uacc1 = fmaf(h1[4 * q + 2], w4.z, uacc1);
        uacc1 = fmaf(h1[4 * q + 3], w4.w, uacc1);
    }

    out[p0] = __expf(sacc0);
    out[4 * N + p0] = __expf(uacc0);
    g_h0[p0] = make_float4(h0[0],  h0[1],  h0[2],  h0[3]);
    g_h1[p0] = make_float4(h0[4],  h0[5],  h0[6],  h0[7]);
    g_h2[p0] = make_float4(h0[8],  h0[9],  h0[10], h0[11]);
    g_h3[p0] = make_float4(h0[12], h0[13], h0[14], h0[15]);
    if (has1) {
        out[p1] = __expf(sacc1);
        out[4 * N + p1] = __expf(uacc1);
        g_h0[p1] = make_float4(h1[0],  h1[1],  h1[2],  h1[3]);
        g_h1[p1] = make_float4(h1[4],  h1[5],  h1[6],  h1[7]);
        g_h2[p1] = make_float4(h1[8],  h1[9],  h1[10], h1[11]);
        g_h3[p1] = make_float4(h1[12], h1[13], h1[14], h1[15]);
    }
}

// ============================ Kernel 2: wmma (HMMA) render ==================
// 256 points per block (8 warps, each owns a 32-row M strip).
// A0=[sh|h] (K=32) -> z1=relu(A0@W1) (64) -> z2=relu(z1@W2) (64)
//   -> rgb=sigmoid(z2@W3[:, :3])
// Split-bf16 (Markidis): x = hi + lo; D = hi*hi + hi*lo + lo*hi in fp32 acc.

#define MPTS 256         // points per block
#define LDA  72          // bf16 staging ldm (multiple of 8)
#define LDC  68          // fp32 C ldm (multiple of 4; stride%8==4 -> 4-way max)
#define LDB3 24          // layer-3 B ldm
// dynamic smem byte offsets
#define R_AH   0                              // [256][72] bf16 = 36864
#define R_AL   36864                          // 36864
#define R_C    73728                          // [256][68] f32 = 69632
#define R_B1H  143360                         // [32][72] bf16 = 4608
#define R_B1L  147968
#define R_B2H  152576                         // [64][72] bf16 = 9216
#define R_B2L  161792
#define R_B3H  171008                         // [64][24] bf16 = 3072
#define R_B3L  174080
#define R_SMEM 177152

using namespace nvcuda;

__device__ __forceinline__ void split_w(float v, __nv_bfloat16& hi, __nv_bfloat16& lo) {
    hi = __float2bfloat16(v);
    lo = __float2bfloat16(v - __bfloat162float(hi));
}

template <int KTILES, int NTILES, int BLDM>
__device__ __forceinline__ void wmma_layer(const __nv_bfloat16* sAH,
                                           const __nv_bfloat16* sAL,
                                           const __nv_bfloat16* sBH,
                                           const __nv_bfloat16* sBL,
                                           float* sC, int wid)
{
    const int m0 = wid * 32;
    #pragma unroll
    for (int nt = 0; nt < NTILES; nt++) {
        wmma::fragment<wmma::matrix_b, 16, 16, 16, __nv_bfloat16, wmma::row_major> bh[KTILES], bl[KTILES];
        #pragma unroll
        for (int k = 0; k < KTILES; k++) {
            wmma::load_matrix_sync(bh[k], sBH + k * 16 * BLDM + nt * 16, BLDM);
            wmma::load_matrix_sync(bl[k], sBL + k * 16 * BLDM + nt * 16, BLDM);
        }
        #pragma unroll
        for (int ms = 0; ms < 2; ms++) {
            const int m = m0 + ms * 16;
            wmma::fragment<wmma::accumulator, 16, 16, 16, float> acc;
            wmma::fill_fragment(acc, 0.0f);
            #pragma unroll
            for (int k = 0; k < KTILES; k++) {
                wmma::fragment<wmma::matrix_a, 16, 16, 16, __nv_bfloat16, wmma::row_major> ah, al;
                wmma::load_matrix_sync(ah, sAH + m * LDA + k * 16, LDA);
                wmma::load_matrix_sync(al, sAL + m * LDA + k * 16, LDA);
                wmma::mma_sync(acc, ah, bh[k], acc);
                wmma::mma_sync(acc, ah, bl[k], acc);
                wmma::mma_sync(acc, al, bh[k], acc);
            }
            wmma::store_matrix_sync(sC + m * LDC + nt * 16, acc, LDC, wmma::mem_row_major);
        }
    }
}

__global__ __launch_bounds__(256)
void ngp_render_wmma(const float* __restrict__ gd,
                     const float* __restrict__ wr1,
                     const float* __restrict__ wr2,
                     const float* __restrict__ wr3,
                     float* __restrict__ out,
                     int N)
{
    extern __shared__ char dsm[];
    __nv_bfloat16* sAH  = (__nv_bfloat16*)(dsm + R_AH);
    __nv_bfloat16* sAL  = (__nv_bfloat16*)(dsm + R_AL);
    float*         sC   = (float*)(dsm + R_C);
    __nv_bfloat16* sB1H = (__nv_bfloat16*)(dsm + R_B1H);
    __nv_bfloat16* sB1L = (__nv_bfloat16*)(dsm + R_B1L);
    __nv_bfloat16* sB2H = (__nv_bfloat16*)(dsm + R_B2H);
    __nv_bfloat16* sB2L = (__nv_bfloat16*)(dsm + R_B2L);
    __nv_bfloat16* sB3H = (__nv_bfloat16*)(dsm + R_B3H);
    __nv_bfloat16* sB3L = (__nv_bfloat16*)(dsm + R_B3L);

    const int tid = threadIdx.x;
    const int wid = tid >> 5;

    // -------- stage split-bf16 weights ([K][N] row-major, padded ldm) --------
    for (int t = tid; t < 32 * 64; t += 256) {
        int k = t >> 6, n = t & 63;
        __nv_bfloat16 hi, lo;
        split_w(wr1[k * 64 + n], hi, lo);
        sB1H[k * LDA + n] = hi;
        sB1L[k * LDA + n] = lo;
    }
    for (int t = tid; t < 64 * 64; t += 256) {
        int k = t >> 6, n = t & 63;
        __nv_bfloat16 hi, lo;
        split_w(wr2[k * 64 + n], hi, lo);
        sB2H[k * LDA + n] = hi;
        sB2L[k * LDA + n] = lo;
    }
    for (int t = tid; t < 64 * 16; t += 256) {
        int k = t >> 4, n = t & 15;
        float w = (n < 3) ? wr3[k * 3 + n] : 0.0f;
        __nv_bfloat16 hi, lo;
        split_w(w, hi, lo);
        sB3H[k * LDB3 + n] = hi;
        sB3L[k * LDB3 + n] = lo;
    }

    // -------- build A0 = [sh | h] (row = tid, K=32) ---------------------------
    const int p = blockIdx.x * MPTS + tid;
    const int pc = (p < N) ? p : (N - 1);
    float a0[32];
    {
        float4 v;
        v = g_h0[pc]; a0[16]=v.x; a0[17]=v.y; a0[18]=v.z; a0[19]=v.w;
        v = g_h1[pc]; a0[20]=v.x; a0[21]=v.y; a0[22]=v.z; a0[23]=v.w;
        v = g_h2[pc]; a0[24]=v.x; a0[25]=v.y; a0[26]=v.z; a0[27]=v.w;
        v = g_h3[pc]; a0[28]=v.x; a0[29]=v.y; a0[30]=v.z; a0[31]=v.w;
        float vx = __fadd_rn(__fadd_rn(gd[3 * pc + 0], 1.0f), -1.0f);
        float vy = __fadd_rn(__fadd_rn(gd[3 * pc + 1], 1.0f), -1.0f);
        float vz = __fadd_rn(__fadd_rn(gd[3 * pc + 2], 1.0f), -1.0f);
        float x2 = vx * vx, y2 = vy * vy, z2 = vz * vz;
        float xy = vx * vy, yz = vy * vz, xz = vx * vz;
        a0[0]  = 0.28209479177387814f;
        a0[1]  = -0.48860251190291987f * vy;
        a0[2]  = 0.48860251190291987f * vz;
        a0[3]  = -0.48860251190291987f * vx;
        a0[4]  = 1.0925484305920792f * xy;
        a0[5]  = -1.0925484305920792f * yz;
        a0[6]  = 0.94617469575756f * z2 - 0.31539156525252f;
        a0[7]  = -1.0925484305920792f * xz;
        a0[8]  = 0.5462742152960396f * (x2 - y2);
        a0[9]  = 0.5900435899266435f * vy * (-3.0f * x2 + y2);
        a0[10] = 2.890611442640554f * xy * vz;
        a0[11] = 0.4570457994644657f * vy * (1.0f - 5.0f * z2);
        a0[12] = 0.3731763325901154f * vz * (5.0f * z2 - 3.0f);
        a0[13] = 0.4570457994644657f * vx * (1.0f - 5.0f * z2);
        a0[14] = 1.445305721320277f * vz * (x2 - y2);
        a0[15] = 0.5900435899266435f * vx * (-x2 + 3.0f * y2);
    }
    #pragma unroll
    for (int k = 0; k < 32; k++) {
        __nv_bfloat16 hi, lo;
        split_w(a0[k], hi, lo);
        sAH[tid * LDA + k] = hi;
        sAL[tid * LDA + k] = lo;
    }
    __syncthreads();

    // -------- layer 1: [256x32] @ W1[32x64] -----------------------------------
    wmma_layer<2, 4, LDA>(sAH, sAL, sB1H, sB1L, sC, wid);
    __syncthreads();
    #pragma unroll
    for (int j = 0; j < 64; j += 4) {
        float4 v = *(const float4*)&sC[tid * LDC + j];
        v.x = fmaxf(v.x, 0.0f); v.y = fmaxf(v.y, 0.0f);
        v.z = fmaxf(v.z, 0.0f); v.w = fmaxf(v.w, 0.0f);
        __nv_bfloat16 h, l;
        split_w(v.x, h, l); sAH[tid * LDA + j + 0] = h; sAL[tid * LDA + j + 0] = l;
        split_w(v.y, h, l); sAH[tid * LDA + j + 1] = h; sAL[tid * LDA + j + 1] = l;
        split_w(v.z, h, l); sAH[tid * LDA + j + 2] = h; sAL[tid * LDA + j + 2] = l;
        split_w(v.w, h, l); sAH[tid * LDA + j + 3] = h; sAL[tid * LDA + j + 3] = l;
    }
    __syncthreads();

    // -------- layer 2: [256x64] @ W2[64x64] -----------------------------------
    wmma_layer<4, 4, LDA>(sAH, sAL, sB2H, sB2L, sC, wid);
    __syncthreads();
    #pragma unroll
    for (int j = 0; j < 64; j += 4) {
        float4 v = *(const float4*)&sC[tid * LDC + j];
        v.x = fmaxf(v.x, 0.0f); v.y = fmaxf(v.y, 0.0f);
        v.z = fmaxf(v.z, 0.0f); v.w = fmaxf(v.w, 0.0f);
        __nv_bfloat16 h, l;
        split_w(v.x, h, l); sAH[tid * LDA + j + 0] = h; sAL[tid * LDA + j + 0] = l;
        split_w(v.y, h, l); sAH[tid * LDA + j + 1] = h; sAL[tid * LDA + j + 1] = l;
        split_w(v.z, h, l); sAH[tid * LDA + j + 2] = h; sAL[tid * LDA + j + 2] = l;
        split_w(v.w, h, l); sAH[tid * LDA + j + 3] = h; sAL[tid * LDA + j + 3] = l;
    }
    __syncthreads();

    // -------- layer 3: [256x64] @ W3[64x16(pad)] ------------------------------
    wmma_layer<4, 1, LDB3>(sAH, sAL, sB3H, sB3L, sC, wid);
    __syncthreads();

    if (p < N) {
        float r0 = sC[tid * LDC + 0];
        float r1 = sC[tid * LDC + 1];
        float r2 = sC[tid * LDC + 2];
        out[N + 3 * p + 0] = __fdividef(1.0f, 1.0f + __expf(-r0));
        out[N + 3 * p + 1] = __fdividef(1.0f, 1.0f + __expf(-r1));
        out[N + 3 * p + 2] = __fdividef(1.0f, 1.0f + __expf(-r2));
    }
}

extern "C" void kernel_launch(void* const* d_in, const int* in_sizes, int n_in,
                              void* d_out, int out_size) {
    const float* x     = (const float*)d_in[0];
    const float* d     = (const float*)d_in[1];
    const float* table = (const float*)d_in[2];
    const float* w1    = (const float*)d_in[3];
    const float* w2    = (const float*)d_in[4];
    const float* wa1   = (const float*)d_in[5];
    const float* wa2   = (const float*)d_in[6];
    const float* wu1   = (const float*)d_in[7];
    const float* wu2   = (const float*)d_in[8];
    const float* wr1   = (const float*)d_in[9];
    const float* wr2   = (const float*)d_in[10];
    const float* wr3   = (const float*)d_in[11];
    float* out = (float*)d_out;

    int N = in_sizes[0] / 3;

    LevelP lp;
    double Bv = exp(log(2048.0 / 16.0) / 15.0);
    uint32_t mask = 0;
    for (int l = 0; l < NLEV; l++) {
        double s = 16.0 * pow(Bv, (double)l) - 1.0;
        lp.scale[l] = (float)s;
        long long r = (long long)ceil(s) + 1;
        lp.res[l] = (uint32_t)r;
        if (r * r * r <= (long long)TBL) mask |= (1u << l);
    }
    lp.dense_mask = mask;

    static int smem_set = 0;
    if (!smem_set) {
        cudaFuncSetAttribute(ngp_render_wmma,
                             cudaFuncAttributeMaxDynamicSharedMemorySize,
                             R_SMEM);
        smem_set = 1;
    }

    int eblocks = (N + 255) / 256;
    ngp_encode_kernel<<<eblocks, 128>>>(x, table, w1, w2, wa1, wa2,
                                        wu1, wu2, out, N, lp);
    int rblocks = (N + MPTS - 1) / MPTS;
    ngp_render_wmma<<<rblocks, 256, R_SMEM>>>(d, wr1, wr2, wr3, out, N);
}

// round 14
// speedup vs baseline: 1.0949x; 1.0350x over previous
#include <cuda_runtime.h>
#include <cuda_bf16.h>
#include <mma.h>
#include <math.h>
#include <stdint.h>

#define NLEV 16
#define TBL (1u << 19)
#define NMAX (1 << 20)

struct LevelP {
    float scale[NLEV];
    uint32_t res[NLEV];
    uint32_t dense_mask;
};

// Planar float4 scratch for h[16] per point: 4 planes x 16 MB = 64 MB.
__device__ float4 g_h0[NMAX];
__device__ float4 g_h1[NMAX];
__device__ float4 g_h2[NMAX];
__device__ float4 g_h3[NMAX];

// ---------------- grid encode for one point (enc stays in regs) -------------
__device__ __forceinline__ void grid_encode_pt(float px, float py, float pz,
                                               const float* __restrict__ table,
                                               const LevelP& lp, float* enc)
{
    #pragma unroll
    for (int l = 0; l < NLEV; l++) {
        const float s = lp.scale[l];
        const uint32_t res = lp.res[l];
        const bool dense = (lp.dense_mask >> l) & 1u;

        float posx = __fadd_rn(__fmul_rn(px, s), 0.5f);
        float posy = __fadd_rn(__fmul_rn(py, s), 0.5f);
        float posz = __fadd_rn(__fmul_rn(pz, s), 0.5f);
        float gxf = floorf(posx), gyf = floorf(posy), gzf = floorf(posz);
        float fx = posx - gxf, fy = posy - gyf, fz = posz - gzf;
        uint32_t X = (uint32_t)gxf, Y = (uint32_t)gyf, Z = (uint32_t)gzf;

        const float2* tab = (const float2*)table + (size_t)l * TBL;

        uint32_t hy0 = Y * 2654435761u;
        uint32_t hy1 = (Y + 1u) * 2654435761u;
        uint32_t hz0 = Z * 805459861u;
        uint32_t hz1 = (Z + 1u) * 805459861u;
        uint32_t dy0 = Y * res,        dy1 = (Y + 1u) * res;
        uint32_t dz0 = Z * res * res,  dz1 = (Z + 1u) * res * res;

        float wx1 = fx, wx0 = 1.0f - fx;
        float wy1 = fy, wy0 = 1.0f - fy;
        float wz1 = fz, wz0 = 1.0f - fz;

        float e0 = 0.0f, e1 = 0.0f;
        #pragma unroll
        for (int c = 0; c < 8; c++) {
            const uint32_t bi = (c >> 2) & 1, bj = (c >> 1) & 1, bk = c & 1;
            uint32_t cx = X + bi;
            uint32_t idx;
            if (dense) {
                idx = cx + (bj ? dy1 : dy0) + (bk ? dz1 : dz0);
            } else {
                idx = (cx ^ (bj ? hy1 : hy0) ^ (bk ? hz1 : hz0)) & (TBL - 1u);
            }
            float w = (bi ? wx1 : wx0) * (bj ? wy1 : wy0) * (bk ? wz1 : wz0);
            float2 f = __ldg(tab + idx);
            e0 = fmaf(f.x, w, e0);
            e1 = fmaf(f.y, w, e1);
        }
        enc[2 * l + 0] = e0;
        enc[2 * l + 1] = e1;
    }
}

// ============================ Kernel 1: dual-point encode ===================
__global__ __launch_bounds__(128, 2)
void ngp_encode_kernel(const float* __restrict__ gx,
                       const float* __restrict__ table,
                       const float* __restrict__ w1,
                       const float* __restrict__ w2,
                       const float* __restrict__ wa1,
                       const float* __restrict__ wa2,
                       const float* __restrict__ wu1,
                       const float* __restrict__ wu2,
                       float* __restrict__ out,
                       int N, LevelP lp)
{
    __shared__ __align__(16) float s_w1T[64 * 32];
    __shared__ __align__(16) float s_w2[64 * 16];
    __shared__ __align__(16) float s_wa1T[32 * 16];
    __shared__ __align__(16) float s_wa2[32];
    __shared__ __align__(16) float s_wuf[16];

    const int tid = threadIdx.x;
    for (int t = tid; t < 64 * 32; t += 128) {
        int j = t >> 5, i = t & 31;
        s_w1T[t] = w1[i * 64 + j];
    }
    for (int t = tid; t < 64 * 16; t += 128) s_w2[t] = w2[t];
    for (int t = tid; t < 32 * 16; t += 128) {
        int j = t >> 4, i = t & 15;
        s_wa1T[t] = wa1[i * 32 + j];
    }
    if (tid < 32) s_wa2[tid] = wa2[tid];
    if (tid < 16) {
        float acc = 0.0f;
        for (int j = 0; j < 32; j++) acc = fmaf(wu1[tid * 32 + j], wu2[j], acc);
        s_wuf[tid] = acc;
    }
    __syncthreads();

    const int p0 = blockIdx.x * 256 + tid;
    if (p0 >= N) return;
    int p1 = p0 + 128;
    const bool has1 = (p1 < N);
    if (!has1) p1 = p0;

    float px0 = __fmul_rn(__fadd_rn(gx[3 * p0 + 0], 1.0f), 0.5f);
    float py0 = __fmul_rn(__fadd_rn(gx[3 * p0 + 1], 1.0f), 0.5f);
    float pz0 = __fmul_rn(__fadd_rn(gx[3 * p0 + 2], 1.0f), 0.5f);
    float px1 = __fmul_rn(__fadd_rn(gx[3 * p1 + 0], 1.0f), 0.5f);
    float py1 = __fmul_rn(__fadd_rn(gx[3 * p1 + 1], 1.0f), 0.5f);
    float pz1 = __fmul_rn(__fadd_rn(gx[3 * p1 + 2], 1.0f), 0.5f);

    float enc0[32], enc1[32];
    grid_encode_pt(px0, py0, pz0, table, lp, enc0);
    grid_encode_pt(px1, py1, pz1, table, lp, enc1);

    float h0[16], h1[16];
    #pragma unroll
    for (int k = 0; k < 16; k++) { h0[k] = 0.0f; h1[k] = 0.0f; }
    #pragma unroll 2
    for (int j = 0; j < 64; j++) {
        const float4* wr = (const float4*)&s_w1T[j * 32];
        float a0 = 0.0f, a1 = 0.0f;
        #pragma unroll
        for (int q = 0; q < 8; q++) {
            float4 w4 = wr[q];
            a0 = fmaf(enc0[4 * q + 0], w4.x, a0);
            a0 = fmaf(enc0[4 * q + 1], w4.y, a0);
            a0 = fmaf(enc0[4 * q + 2], w4.z, a0);
            a0 = fmaf(enc0[4 * q + 3], w4.w, a0);
            a1 = fmaf(enc1[4 * q + 0], w4.x, a1);
            a1 = fmaf(enc1[4 * q + 1], w4.y, a1);
            a1 = fmaf(enc1[4 * q + 2], w4.z, a1);
            a1 = fmaf(enc1[4 * q + 3], w4.w, a1);
        }
        float t0 = fmaxf(a0, 0.0f), t1 = fmaxf(a1, 0.0f);
        const float4* w2r = (const float4*)&s_w2[j * 16];
        #pragma unroll
        for (int q = 0; q < 4; q++) {
            float4 w4 = w2r[q];
            h0[4 * q + 0] = fmaf(t0, w4.x, h0[4 * q + 0]);
            h0[4 * q + 1] = fmaf(t0, w4.y, h0[4 * q + 1]);
            h0[4 * q + 2] = fmaf(t0, w4.z, h0[4 * q + 2]);
            h0[4 * q + 3] = fmaf(t0, w4.w, h0[4 * q + 3]);
            h1[4 * q + 0] = fmaf(t1, w4.x, h1[4 * q + 0]);
            h1[4 * q + 1] = fmaf(t1, w4.y, h1[4 * q + 1]);
            h1[4 * q + 2] = fmaf(t1, w4.z, h1[4 * q + 2]);
            h1[4 * q + 3] = fmaf(t1, w4.w, h1[4 * q + 3]);
        }
    }

    float sacc0 = 0.0f, sacc1 = 0.0f;
    #pragma unroll 4
    for (int j = 0; j < 32; j++) {
        const float4* wa = (const float4*)&s_wa1T[j * 16];
        float a0 = 0.0f, a1 = 0.0f;
        #pragma unroll
        for (int q = 0; q < 4; q++) {
            float4 w4 = wa[q];
            a0 = fmaf(h0[4 * q + 0], w4.x, a0);
            a0 = fmaf(h0[4 * q + 1], w4.y, a0);
            a0 = fmaf(h0[4 * q + 2], w4.z, a0);
            a0 = fmaf(h0[4 * q + 3], w4.w, a0);
            a1 = fmaf(h1[4 * q + 0], w4.x, a1);
            a1 = fmaf(h1[4 * q + 1], w4.y, a1);
            a1 = fmaf(h1[4 * q + 2], w4.z, a1);
            a1 = fmaf(h1[4 * q + 3], w4.w, a1);
        }
        float w = s_wa2[j];
        sacc0 = fmaf(fmaxf(a0, 0.0f), w, sacc0);
        sacc1 = fmaf(fmaxf(a1, 0.0f), w, sacc1);
    }

    float uacc0 = 0.0f, uacc1 = 0.0f;
    #pragma unroll
    for (int q = 0; q < 4; q++) {
        float4 w4 = ((const float4*)s_wuf)[q];
        uacc0 = fmaf(h0[4 * q + 0], w4.x, uacc0);
        uacc0 = fmaf(h0[4 * q + 1], w4.y, uacc0);
        uacc0 = fmaf(h0[4 * q + 2], w4.z, uacc0);
        uacc0 = fmaf(h0[4 * q + 3], w4.w, uacc0);
        uacc1 = fmaf(h1[4 * q + 0], w4.x, uacc1);
        uacc1 = fmaf(h1[4 * q + 1], w4.y, uacc1);
        uacc1 = fmaf(h1[4 * q + 2], w4.z, uacc1);
        uacc1 = fmaf(h1[4 * q + 3], w4.w, uacc1);
    }

    out[p0] = __expf(sacc0);
    out[4 * N + p0] = __expf(uacc0);
    g_h0[p0] = make_float4(h0[0],  h0[1],  h0[2],  h0[3]);
    g_h1[p0] = make_float4(h0[4],  h0[5],  h0[6],  h0[7]);
    g_h2[p0] = make_float4(h0[8],  h0[9],  h0[10], h0[11]);
    g_h3[p0] = make_float4(h0[12], h0[13], h0[14], h0[15]);
    if (has1) {
        out[p1] = __expf(sacc1);
        out[4 * N + p1] = __expf(uacc1);
        g_h0[p1] = make_float4(h1[0],  h1[1],  h1[2],  h1[3]);
        g_h1[p1] = make_float4(h1[4],  h1[5],  h1[6],  h1[7]);
        g_h2[p1] = make_float4(h1[8],  h1[9],  h1[10], h1[11]);
        g_h3[p1] = make_float4(h1[12], h1[13], h1[14], h1[15]);
    }
}

// ============================ Kernel 2: wmma (HMMA) render ==================
// 256 points per block, 8 warps; warp w owns rows 32w..32w+31 in A, C, and
// the next layer's A — activations never cross warps, so after one staging
// __syncthreads the warps run the whole 3-layer chain independently with
// only __syncwarp() between phases.
// Split-bf16 (Markidis): x = hi + lo; D = hi*hi + hi*lo + lo*hi in fp32 acc.

#define MPTS 256         // points per block
#define LDA  72          // bf16 staging ldm (multiple of 8)
#define LDC  68          // fp32 C ldm (multiple of 4; stride%8==4 -> 4-way max)
#define LDB3 24          // layer-3 B ldm
// dynamic smem byte offsets
#define R_AH   0                              // [256][72] bf16 = 36864
#define R_AL   36864                          // 36864
#define R_C    73728                          // [256][68] f32 = 69632
#define R_B1H  143360                         // [32][72] bf16 = 4608
#define R_B1L  147968
#define R_B2H  152576                         // [64][72] bf16 = 9216
#define R_B2L  161792
#define R_B3H  171008                         // [64][24] bf16 = 3072
#define R_B3L  174080
#define R_SMEM 177152

using namespace nvcuda;

__device__ __forceinline__ void split_w(float v, __nv_bfloat16& hi, __nv_bfloat16& lo) {
    hi = __float2bfloat16(v);
    lo = __float2bfloat16(v - __bfloat162float(hi));
}

// Per-warp layer: A hi/lo fragments for both 16-row strips cached in registers
// (loaded once), B fragments per n-tile. No block-wide sync inside.
template <int KTILES, int NTILES, int BLDM>
__device__ __forceinline__ void wmma_layer(const __nv_bfloat16* sAH,
                                           const __nv_bfloat16* sAL,
                                           const __nv_bfloat16* sBH,
                                           const __nv_bfloat16* sBL,
                                           float* sC, int wid)
{
    const int m0 = wid * 32;
    wmma::fragment<wmma::matrix_a, 16, 16, 16, __nv_bfloat16, wmma::row_major> ah[2][KTILES], al[2][KTILES];
    #pragma unroll
    for (int ms = 0; ms < 2; ms++) {
        #pragma unroll
        for (int k = 0; k < KTILES; k++) {
            wmma::load_matrix_sync(ah[ms][k], sAH + (m0 + ms * 16) * LDA + k * 16, LDA);
            wmma::load_matrix_sync(al[ms][k], sAL + (m0 + ms * 16) * LDA + k * 16, LDA);
        }
    }
    #pragma unroll
    for (int nt = 0; nt < NTILES; nt++) {
        wmma::fragment<wmma::matrix_b, 16, 16, 16, __nv_bfloat16, wmma::row_major> bh[KTILES], bl[KTILES];
        #pragma unroll
        for (int k = 0; k < KTILES; k++) {
            wmma::load_matrix_sync(bh[k], sBH + k * 16 * BLDM + nt * 16, BLDM);
            wmma::load_matrix_sync(bl[k], sBL + k * 16 * BLDM + nt * 16, BLDM);
        }
        #pragma unroll
        for (int ms = 0; ms < 2; ms++) {
            wmma::fragment<wmma::accumulator, 16, 16, 16, float> acc;
            wmma::fill_fragment(acc, 0.0f);
            #pragma unroll
            for (int k = 0; k < KTILES; k++) {
                wmma::mma_sync(acc, ah[ms][k], bh[k], acc);
                wmma::mma_sync(acc, ah[ms][k], bl[k], acc);
                wmma::mma_sync(acc, al[ms][k], bh[k], acc);
            }
            wmma::store_matrix_sync(sC + (m0 + ms * 16) * LDC + nt * 16, acc, LDC, wmma::mem_row_major);
        }
    }
}

__global__ __launch_bounds__(256)
void ngp_render_wmma(const float* __restrict__ gd,
                     const float* __restrict__ wr1,
                     const float* __restrict__ wr2,
                     const float* __restrict__ wr3,
                     float* __restrict__ out,
                     int N)
{
    extern __shared__ char dsm[];
    __nv_bfloat16* sAH  = (__nv_bfloat16*)(dsm + R_AH);
    __nv_bfloat16* sAL  = (__nv_bfloat16*)(dsm + R_AL);
    float*         sC   = (float*)(dsm + R_C);
    __nv_bfloat16* sB1H = (__nv_bfloat16*)(dsm + R_B1H);
    __nv_bfloat16* sB1L = (__nv_bfloat16*)(dsm + R_B1L);
    __nv_bfloat16* sB2H = (__nv_bfloat16*)(dsm + R_B2H);
    __nv_bfloat16* sB2L = (__nv_bfloat16*)(dsm + R_B2L);
    __nv_bfloat16* sB3H = (__nv_bfloat16*)(dsm + R_B3H);
    __nv_bfloat16* sB3L = (__nv_bfloat16*)(dsm + R_B3L);

    const int tid = threadIdx.x;
    const int wid = tid >> 5;

    // -------- stage split-bf16 weights ([K][N] row-major, padded ldm) --------
    for (int t = tid; t < 32 * 64; t += 256) {
        int k = t >> 6, n = t & 63;
        __nv_bfloat16 hi, lo;
        split_w(wr1[k * 64 + n], hi, lo);
        sB1H[k * LDA + n] = hi;
        sB1L[k * LDA + n] = lo;
    }
    for (int t = tid; t < 64 * 64; t += 256) {
        int k = t >> 6, n = t & 63;
        __nv_bfloat16 hi, lo;
        split_w(wr2[k * 64 + n], hi, lo);
        sB2H[k * LDA + n] = hi;
        sB2L[k * LDA + n] = lo;
    }
    for (int t = tid; t < 64 * 16; t += 256) {
        int k = t >> 4, n = t & 15;
        float w = (n < 3) ? wr3[k * 3 + n] : 0.0f;
        __nv_bfloat16 hi, lo;
        split_w(w, hi, lo);
        sB3H[k * LDB3 + n] = hi;
        sB3L[k * LDB3 + n] = lo;
    }

    // -------- build A0 = [sh | h] (row = tid, K=32) ---------------------------
    const int p = blockIdx.x * MPTS + tid;
    const int pc = (p < N) ? p : (N - 1);
    float a0[32];
    {
        float4 v;
        v = g_h0[pc]; a0[16]=v.x; a0[17]=v.y; a0[18]=v.z; a0[19]=v.w;
        v = g_h1[pc]; a0[20]=v.x; a0[21]=v.y; a0[22]=v.z; a0[23]=v.w;
        v = g_h2[pc]; a0[24]=v.x; a0[25]=v.y; a0[26]=v.z; a0[27]=v.w;
        v = g_h3[pc]; a0[28]=v.x; a0[29]=v.y; a0[30]=v.z; a0[31]=v.w;
        float vx = __fadd_rn(__fadd_rn(gd[3 * pc + 0], 1.0f), -1.0f);
        float vy = __fadd_rn(__fadd_rn(gd[3 * pc + 1], 1.0f), -1.0f);
        float vz = __fadd_rn(__fadd_rn(gd[3 * pc + 2], 1.0f), -1.0f);
        float x2 = vx * vx, y2 = vy * vy, z2 = vz * vz;
        float xy = vx * vy, yz = vy * vz, xz = vx * vz;
        a0[0]  = 0.28209479177387814f;
        a0[1]  = -0.48860251190291987f * vy;
        a0[2]  = 0.48860251190291987f * vz;
        a0[3]  = -0.48860251190291987f * vx;
        a0[4]  = 1.0925484305920792f * xy;
        a0[5]  = -1.0925484305920792f * yz;
        a0[6]  = 0.94617469575756f * z2 - 0.31539156525252f;
        a0[7]  = -1.0925484305920792f * xz;
        a0[8]  = 0.5462742152960396f * (x2 - y2);
        a0[9]  = 0.5900435899266435f * vy * (-3.0f * x2 + y2);
        a0[10] = 2.890611442640554f * xy * vz;
        a0[11] = 0.4570457994644657f * vy * (1.0f - 5.0f * z2);
        a0[12] = 0.3731763325901154f * vz * (5.0f * z2 - 3.0f);
        a0[13] = 0.4570457994644657f * vx * (1.0f - 5.0f * z2);
        a0[14] = 1.445305721320277f * vz * (x2 - y2);
        a0[15] = 0.5900435899266435f * vx * (-x2 + 3.0f * y2);
    }
    #pragma unroll
    for (int k = 0; k < 32; k++) {
        __nv_bfloat16 hi, lo;
        split_w(a0[k], hi, lo);
        sAH[tid * LDA + k] = hi;
        sAL[tid * LDA + k] = lo;
    }
    __syncthreads();   // weights visible block-wide; from here warps are independent

    // -------- layer 1: [256x32] @ W1[32x64] -----------------------------------
    wmma_layer<2, 4, LDA>(sAH, sAL, sB1H, sB1L, sC, wid);
    __syncwarp();
    #pragma unroll
    for (int j = 0; j < 64; j += 4) {
        float4 v = *(const float4*)&sC[tid * LDC + j];
        v.x = fmaxf(v.x, 0.0f); v.y = fmaxf(v.y, 0.0f);
        v.z = fmaxf(v.z, 0.0f); v.w = fmaxf(v.w, 0.0f);
        __nv_bfloat16 h, l;
        split_w(v.x, h, l); sAH[tid * LDA + j + 0] = h; sAL[tid * LDA + j + 0] = l;
        split_w(v.y, h, l); sAH[tid * LDA + j + 1] = h; sAL[tid * LDA + j + 1] = l;
        split_w(v.z, h, l); sAH[tid * LDA + j + 2] = h; sAL[tid * LDA + j + 2] = l;
        split_w(v.w, h, l); sAH[tid * LDA + j + 3] = h; sAL[tid * LDA + j + 3] = l;
    }
    __syncwarp();

    // -------- layer 2: [256x64] @ W2[64x64] -----------------------------------
    wmma_layer<4, 4, LDA>(sAH, sAL, sB2H, sB2L, sC, wid);
    __syncwarp();
    #pragma unroll
    for (int j = 0; j < 64; j += 4) {
        float4 v = *(const float4*)&sC[tid * LDC + j];
        v.x = fmaxf(v.x, 0.0f); v.y = fmaxf(v.y, 0.0f);
        v.z = fmaxf(v.z, 0.0f); v.w = fmaxf(v.w, 0.0f);
        __nv_bfloat16 h, l;
        split_w(v.x, h, l); sAH[tid * LDA + j + 0] = h; sAL[tid * LDA + j + 0] = l;
        split_w(v.y, h, l); sAH[tid * LDA + j + 1] = h; sAL[tid * LDA + j + 1] = l;
        split_w(v.z, h, l); sAH[tid * LDA + j + 2] = h; sAL[tid * LDA + j + 2] = l;
        split_w(v.w, h, l); sAH[tid * LDA + j + 3] = h; sAL[tid * LDA + j + 3] = l;
    }
    __syncwarp();

    // -------- layer 3: [256x64] @ W3[64x16(pad)] ------------------------------
    wmma_layer<4, 1, LDB3>(sAH, sAL, sB3H, sB3L, sC, wid);
    __syncwarp();

    if (p < N) {
        float r0 = sC[tid * LDC + 0];
        float r1 = sC[tid * LDC + 1];
        float r2 = sC[tid * LDC + 2];
        out[N + 3 * p + 0] = __fdividef(1.0f, 1.0f + __expf(-r0));
        out[N + 3 * p + 1] = __fdividef(1.0f, 1.0f + __expf(-r1));
        out[N + 3 * p + 2] = __fdividef(1.0f, 1.0f + __expf(-r2));
    }
}

extern "C" void kernel_launch(void* const* d_in, const int* in_sizes, int n_in,
                              void* d_out, int out_size) {
    const float* x     = (const float*)d_in[0];
    const float* d     = (const float*)d_in[1];
    const float* table = (const float*)d_in[2];
    const float* w1    = (const float*)d_in[3];
    const float* w2    = (const float*)d_in[4];
    const float* wa1   = (const float*)d_in[5];
    const float* wa2   = (const float*)d_in[6];
    const float* wu1   = (const float*)d_in[7];
    const float* wu2   = (const float*)d_in[8];
    const float* wr1   = (const float*)d_in[9];
    const float* wr2   = (const float*)d_in[10];
    const float* wr3   = (const float*)d_in[11];
    float* out = (float*)d_out;

    int N = in_sizes[0] / 3;

    LevelP lp;
    double Bv = exp(log(2048.0 / 16.0) / 15.0);
    uint32_t mask = 0;
    for (int l = 0; l < NLEV; l++) {
        double s = 16.0 * pow(Bv, (double)l) - 1.0;
        lp.scale[l] = (float)s;
        long long r = (long long)ceil(s) + 1;
        lp.res[l] = (uint32_t)r;
        if (r * r * r <= (long long)TBL) mask |= (1u << l);
    }
    lp.dense_mask = mask;

    static int smem_set = 0;
    if (!smem_set) {
        cudaFuncSetAttribute(ngp_render_wmma,
                             cudaFuncAttributeMaxDynamicSharedMemorySize,
                             R_SMEM);
        smem_set = 1;
    }

    int eblocks = (N + 255) / 256;
    ngp_encode_kernel<<<eblocks, 128>>>(x, table, w1, w2, wa1, wa2,
                                        wu1, wu2, out, N, lp);
    int rblocks = (N + MPTS - 1) / MPTS;
    ngp_render_wmma<<<rblocks, 256, R_SMEM>>>(d, wr1, wr2, wr3, out, N);
}

// round 15
// speedup vs baseline: 1.2067x; 1.1021x over previous
#include <cuda_runtime.h>
#include <cuda_bf16.h>
#include <mma.h>
#include <math.h>
#include <stdint.h>

#define NLEV 16
#define TBL (1u << 19)
#define NMAX (1 << 20)

struct LevelP {
    float scale[NLEV];
    uint32_t res[NLEV];
    uint32_t dense_mask;
};

// Planar float4 scratch for h[16] per point: 4 planes x 16 MB = 64 MB.
__device__ float4 g_h0[NMAX];
__device__ float4 g_h1[NMAX];
__device__ float4 g_h2[NMAX];
__device__ float4 g_h3[NMAX];

// ---------------- grid encode for one point (enc stays in regs) -------------
__device__ __forceinline__ void grid_encode_pt(float px, float py, float pz,
                                               const float* __restrict__ table,
                                               const LevelP& lp, float* enc)
{
    #pragma unroll
    for (int l = 0; l < NLEV; l++) {
        const float s = lp.scale[l];
        const uint32_t res = lp.res[l];
        const bool dense = (lp.dense_mask >> l) & 1u;

        float posx = __fadd_rn(__fmul_rn(px, s), 0.5f);
        float posy = __fadd_rn(__fmul_rn(py, s), 0.5f);
        float posz = __fadd_rn(__fmul_rn(pz, s), 0.5f);
        float gxf = floorf(posx), gyf = floorf(posy), gzf = floorf(posz);
        float fx = posx - gxf, fy = posy - gyf, fz = posz - gzf;
        uint32_t X = (uint32_t)gxf, Y = (uint32_t)gyf, Z = (uint32_t)gzf;

        const float2* tab = (const float2*)table + (size_t)l * TBL;

        uint32_t hy0 = Y * 2654435761u;
        uint32_t hy1 = (Y + 1u) * 2654435761u;
        uint32_t hz0 = Z * 805459861u;
        uint32_t hz1 = (Z + 1u) * 805459861u;
        uint32_t dy0 = Y * res,        dy1 = (Y + 1u) * res;
        uint32_t dz0 = Z * res * res,  dz1 = (Z + 1u) * res * res;

        float wx1 = fx, wx0 = 1.0f - fx;
        float wy1 = fy, wy0 = 1.0f - fy;
        float wz1 = fz, wz0 = 1.0f - fz;

        float e0 = 0.0f, e1 = 0.0f;
        #pragma unroll
        for (int c = 0; c < 8; c++) {
            const uint32_t bi = (c >> 2) & 1, bj = (c >> 1) & 1, bk = c & 1;
            uint32_t cx = X + bi;
            uint32_t idx;
            if (dense) {
                idx = cx + (bj ? dy1 : dy0) + (bk ? dz1 : dz0);
            } else {
                idx = (cx ^ (bj ? hy1 : hy0) ^ (bk ? hz1 : hz0)) & (TBL - 1u);
            }
            float w = (bi ? wx1 : wx0) * (bj ? wy1 : wy0) * (bk ? wz1 : wz0);
            float2 f = __ldg(tab + idx);
            e0 = fmaf(f.x, w, e0);
            e1 = fmaf(f.y, w, e1);
        }
        enc[2 * l + 0] = e0;
        enc[2 * l + 1] = e1;
    }
}

// ============================ Kernel 1: dual-point encode ===================
__global__ __launch_bounds__(128, 2)
void ngp_encode_kernel(const float* __restrict__ gx,
                       const float* __restrict__ table,
                       const float* __restrict__ w1,
                       const float* __restrict__ w2,
                       const float* __restrict__ wa1,
                       const float* __restrict__ wa2,
                       const float* __restrict__ wu1,
                       const float* __restrict__ wu2,
                       float* __restrict__ out,
                       int N, LevelP lp)
{
    __shared__ __align__(16) float s_w1T[64 * 32];
    __shared__ __align__(16) float s_w2[64 * 16];
    __shared__ __align__(16) float s_wa1T[32 * 16];
    __shared__ __align__(16) float s_wa2[32];
    __shared__ __align__(16) float s_wuf[16];

    const int tid = threadIdx.x;
    for (int t = tid; t < 64 * 32; t += 128) {
        int j = t >> 5, i = t & 31;
        s_w1T[t] = w1[i * 64 + j];
    }
    for (int t = tid; t < 64 * 16; t += 128) s_w2[t] = w2[t];
    for (int t = tid; t < 32 * 16; t += 128) {
        int j = t >> 4, i = t & 15;
        s_wa1T[t] = wa1[i * 32 + j];
    }
    if (tid < 32) s_wa2[tid] = wa2[tid];
    if (tid < 16) {
        float acc = 0.0f;
        for (int j = 0; j < 32; j++) acc = fmaf(wu1[tid * 32 + j], wu2[j], acc);
        s_wuf[tid] = acc;
    }
    __syncthreads();

    const int p0 = blockIdx.x * 256 + tid;
    if (p0 >= N) return;
    int p1 = p0 + 128;
    const bool has1 = (p1 < N);
    if (!has1) p1 = p0;

    float px0 = __fmul_rn(__fadd_rn(gx[3 * p0 + 0], 1.0f), 0.5f);
    float py0 = __fmul_rn(__fadd_rn(gx[3 * p0 + 1], 1.0f), 0.5f);
    float pz0 = __fmul_rn(__fadd_rn(gx[3 * p0 + 2], 1.0f), 0.5f);
    float px1 = __fmul_rn(__fadd_rn(gx[3 * p1 + 0], 1.0f), 0.5f);
    float py1 = __fmul_rn(__fadd_rn(gx[3 * p1 + 1], 1.0f), 0.5f);
    float pz1 = __fmul_rn(__fadd_rn(gx[3 * p1 + 2], 1.0f), 0.5f);

    float enc0[32], enc1[32];
    grid_encode_pt(px0, py0, pz0, table, lp, enc0);
    grid_encode_pt(px1, py1, pz1, table, lp, enc1);

    float h0[16], h1[16];
    #pragma unroll
    for (int k = 0; k < 16; k++) { h0[k] = 0.0f; h1[k] = 0.0f; }
    #pragma unroll 2
    for (int j = 0; j < 64; j++) {
        const float4* wr = (const float4*)&s_w1T[j * 32];
        float a0 = 0.0f, a1 = 0.0f;
        #pragma unroll
        for (int q = 0; q < 8; q++) {
            float4 w4 = wr[q];
            a0 = fmaf(enc0[4 * q + 0], w4.x, a0);
            a0 = fmaf(enc0[4 * q + 1], w4.y, a0);
            a0 = fmaf(enc0[4 * q + 2], w4.z, a0);
            a0 = fmaf(enc0[4 * q + 3], w4.w, a0);
            a1 = fmaf(enc1[4 * q + 0], w4.x, a1);
            a1 = fmaf(enc1[4 * q + 1], w4.y, a1);
            a1 = fmaf(enc1[4 * q + 2], w4.z, a1);
            a1 = fmaf(enc1[4 * q + 3], w4.w, a1);
        }
        float t0 = fmaxf(a0, 0.0f), t1 = fmaxf(a1, 0.0f);
        const float4* w2r = (const float4*)&s_w2[j * 16];
        #pragma unroll
        for (int q = 0; q < 4; q++) {
            float4 w4 = w2r[q];
            h0[4 * q + 0] = fmaf(t0, w4.x, h0[4 * q + 0]);
            h0[4 * q + 1] = fmaf(t0, w4.y, h0[4 * q + 1]);
            h0[4 * q + 2] = fmaf(t0, w4.z, h0[4 * q + 2]);
            h0[4 * q + 3] = fmaf(t0, w4.w, h0[4 * q + 3]);
            h1[4 * q + 0] = fmaf(t1, w4.x, h1[4 * q + 0]);
            h1[4 * q + 1] = fmaf(t1, w4.y, h1[4 * q + 1]);
            h1[4 * q + 2] = fmaf(t1, w4.z, h1[4 * q + 2]);
            h1[4 * q + 3] = fmaf(t1, w4.w, h1[4 * q + 3]);
        }
    }

    float sacc0 = 0.0f, sacc1 = 0.0f;
    #pragma unroll 4
    for (int j = 0; j < 32; j++) {
        const float4* wa = (const float4*)&s_wa1T[j * 16];
        float a0 = 0.0f, a1 = 0.0f;
        #pragma unroll
        for (int q = 0; q < 4; q++) {
            float4 w4 = wa[q];
            a0 = fmaf(h0[4 * q + 0], w4.x, a0);
            a0 = fmaf(h0[4 * q + 1], w4.y, a0);
            a0 = fmaf(h0[4 * q + 2], w4.z, a0);
            a0 = fmaf(h0[4 * q + 3], w4.w, a0);
            a1 = fmaf(h1[4 * q + 0], w4.x, a1);
            a1 = fmaf(h1[4 * q + 1], w4.y, a1);
            a1 = fmaf(h1[4 * q + 2], w4.z, a1);
            a1 = fmaf(h1[4 * q + 3], w4.w, a1);
        }
        float w = s_wa2[j];
        sacc0 = fmaf(fmaxf(a0, 0.0f), w, sacc0);
        sacc1 = fmaf(fmaxf(a1, 0.0f), w, sacc1);
    }

    float uacc0 = 0.0f, uacc1 = 0.0f;
    #pragma unroll
    for (int q = 0; q < 4; q++) {
        float4 w4 = ((const float4*)s_wuf)[q];
        uacc0 = fmaf(h0[4 * q + 0], w4.x, uacc0);
        uacc0 = fmaf(h0[4 * q + 1], w4.y, uacc0);
        uacc0 = fmaf(h0[4 * q + 2], w4.z, uacc0);
        uacc0 = fmaf(h0[4 * q + 3], w4.w, uacc0);
        uacc1 = fmaf(h1[4 * q + 0], w4.x, uacc1);
        uacc1 = fmaf(h1[4 * q + 1], w4.y, uacc1);
        uacc1 = fmaf(h1[4 * q + 2], w4.z, uacc1);
        uacc1 = fmaf(h1[4 * q + 3], w4.w, uacc1);
    }

    out[p0] = __expf(sacc0);
    out[4 * N + p0] = __expf(uacc0);
    g_h0[p0] = make_float4(h0[0],  h0[1],  h0[2],  h0[3]);
    g_h1[p0] = make_float4(h0[4],  h0[5],  h0[6],  h0[7]);
    g_h2[p0] = make_float4(h0[8],  h0[9],  h0[10], h0[11]);
    g_h3[p0] = make_float4(h0[12], h0[13], h0[14], h0[15]);
    if (has1) {
        out[p1] = __expf(sacc1);
        out[4 * N + p1] = __expf(uacc1);
        g_h0[p1] = make_float4(h1[0],  h1[1],  h1[2],  h1[3]);
        g_h1[p1] = make_float4(h1[4],  h1[5],  h1[6],  h1[7]);
        g_h2[p1] = make_float4(h1[8],  h1[9],  h1[10], h1[11]);
        g_h3[p1] = make_float4(h1[12], h1[13], h1[14], h1[15]);
    }
}

// ============================ Kernel 2: wmma (HMMA) render ==================
// 384 points per block, 12 warps; warp w owns rows 32w..32w+31. Activations
// never cross warps: after one staging __syncthreads, each warp runs the full
// 3-layer chain independently (__syncwarp only). ReLU applied directly on the
// accumulator fragments in registers; re-layout acc->matrix_a goes through a
// tiny per-warp 16x16 scratch tile (no block-wide C buffer).
// Split-bf16 (Markidis): x = hi + lo; D = hi*hi + hi*lo + lo*hi in fp32 acc.

#define MPTS 384
#define NWARP 12
#define LDA  72          // bf16 staging ldm (multiple of 8)
#define LDS_ 20          // per-warp f32 scratch ldm (multiple of 4)
#define LDB3 24          // layer-3 B ldm
// dynamic smem byte offsets
#define R_AH   0                              // [384][72] bf16 = 55296
#define R_AL   55296                          // 55296
#define R_B1H  110592                         // [32][72] bf16 = 4608
#define R_B1L  115200
#define R_B2H  119808                         // [64][72] bf16 = 9216
#define R_B2L  129024
#define R_B3H  138240                         // [64][24] bf16 = 3072
#define R_B3L  141312
#define R_SCR  144384                         // 12 x [16][20] f32 = 15360
#define R_SMEM 159744

using namespace nvcuda;

__device__ __forceinline__ void split_w(float v, __nv_bfloat16& hi, __nv_bfloat16& lo) {
    hi = __float2bfloat16(v);
    lo = __float2bfloat16(v - __bfloat162float(hi));
}

__device__ __forceinline__ uint32_t pack_bf2(__nv_bfloat16 a, __nv_bfloat16 b) {
    __nv_bfloat162 t;
    t.x = a; t.y = b;
    return *(uint32_t*)&t;
}

// One layer with relu: acc fragments relu'd in registers, re-laid-out via the
// per-warp scratch tile, split-bf16 written back into sAH/sAL (this layer's A
// fragments are already cached in registers, so in-place overwrite is safe).
template <int KTILES, int NTILES>
__device__ __forceinline__ void wmma_layer_relu(__nv_bfloat16* sAH,
                                                __nv_bfloat16* sAL,
                                                const __nv_bfloat16* sBH,
                                                const __nv_bfloat16* sBL,
                                                float* scr, int wid, int lane)
{
    const int m0 = wid * 32;
    wmma::fragment<wmma::matrix_a, 16, 16, 16, __nv_bfloat16, wmma::row_major> ah[2][KTILES], al[2][KTILES];
    #pragma unroll
    for (int ms = 0; ms < 2; ms++) {
        #pragma unroll
        for (int k = 0; k < KTILES; k++) {
            wmma::load_matrix_sync(ah[ms][k], sAH + (m0 + ms * 16) * LDA + k * 16, LDA);
            wmma::load_matrix_sync(al[ms][k], sAL + (m0 + ms * 16) * LDA + k * 16, LDA);
        }
    }
    const int r  = lane & 15;        // scratch row this lane reads
    const int ch = lane >> 4;        // which 8-col half
    #pragma unroll
    for (int nt = 0; nt < NTILES; nt++) {
        wmma::fragment<wmma::matrix_b, 16, 16, 16, __nv_bfloat16, wmma::row_major> bh[KTILES], bl[KTILES];
        #pragma unroll
        for (int k = 0; k < KTILES; k++) {
            wmma::load_matrix_sync(bh[k], sBH + k * 16 * LDA + nt * 16, LDA);
            wmma::load_matrix_sync(bl[k], sBL + k * 16 * LDA + nt * 16, LDA);
        }
        #pragma unroll
        for (int ms = 0; ms < 2; ms++) {
            wmma::fragment<wmma::accumulator, 16, 16, 16, float> acc;
            wmma::fill_fragment(acc, 0.0f);
            #pragma unroll
            for (int k = 0; k < KTILES; k++) {
                wmma::mma_sync(acc, ah[ms][k], bh[k], acc);
                wmma::mma_sync(acc, ah[ms][k], bl[k], acc);
                wmma::mma_sync(acc, al[ms][k], bh[k], acc);
            }
            #pragma unroll
            for (int t = 0; t < acc.num_elements; t++)
                acc.x[t] = fmaxf(acc.x[t], 0.0f);           // relu in registers
            wmma::store_matrix_sync(scr, acc, LDS_, wmma::mem_row_major);
            __syncwarp();
            // re-layout: lane reads 8 floats of its row-half, split-writes bf16
            float4 v0 = *(const float4*)&scr[r * LDS_ + ch * 8];
            float4 v1 = *(const float4*)&scr[r * LDS_ + ch * 8 + 4];
            float vv[8] = {v0.x, v0.y, v0.z, v0.w, v1.x, v1.y, v1.z, v1.w};
            uint32_t hw[4], lw[4];
            #pragma unroll
            for (int j = 0; j < 4; j++) {
                __nv_bfloat16 h0, l0, h1, l1;
                split_w(vv[2 * j + 0], h0, l0);
                split_w(vv[2 * j + 1], h1, l1);
                hw[j] = pack_bf2(h0, h1);
                lw[j] = pack_bf2(l0, l1);
            }
            const int row = m0 + ms * 16 + r;
            const int col = nt * 16 + ch * 8;
            *(uint4*)&sAH[row * LDA + col] = make_uint4(hw[0], hw[1], hw[2], hw[3]);
            *(uint4*)&sAL[row * LDA + col] = make_uint4(lw[0], lw[1], lw[2], lw[3]);
            __syncwarp();
        }
    }
}

__global__ __launch_bounds__(MPTS)
void ngp_render_wmma(const float* __restrict__ gd,
                     const float* __restrict__ wr1,
                     const float* __restrict__ wr2,
                     const float* __restrict__ wr3,
                     float* __restrict__ out,
                     int N)
{
    extern __shared__ __align__(16) char dsm[];
    __nv_bfloat16* sAH  = (__nv_bfloat16*)(dsm + R_AH);
    __nv_bfloat16* sAL  = (__nv_bfloat16*)(dsm + R_AL);
    __nv_bfloat16* sB1H = (__nv_bfloat16*)(dsm + R_B1H);
    __nv_bfloat16* sB1L = (__nv_bfloat16*)(dsm + R_B1L);
    __nv_bfloat16* sB2H = (__nv_bfloat16*)(dsm + R_B2H);
    __nv_bfloat16* sB2L = (__nv_bfloat16*)(dsm + R_B2L);
    __nv_bfloat16* sB3H = (__nv_bfloat16*)(dsm + R_B3H);
    __nv_bfloat16* sB3L = (__nv_bfloat16*)(dsm + R_B3L);

    const int tid = threadIdx.x;
    const int wid = tid >> 5;
    const int lane = tid & 31;
    float* scr = (float*)(dsm + R_SCR) + wid * (16 * LDS_);

    // -------- stage split-bf16 weights ([K][N] row-major, padded ldm) --------
    for (int t = tid; t < 32 * 64; t += MPTS) {
        int k = t >> 6, n = t & 63;
        __nv_bfloat16 hi, lo;
        split_w(wr1[k * 64 + n], hi, lo);
        sB1H[k * LDA + n] = hi;
        sB1L[k * LDA + n] = lo;
    }
    for (int t = tid; t < 64 * 64; t += MPTS) {
        int k = t >> 6, n = t & 63;
        __nv_bfloat16 hi, lo;
        split_w(wr2[k * 64 + n], hi, lo);
        sB2H[k * LDA + n] = hi;
        sB2L[k * LDA + n] = lo;
    }
    for (int t = tid; t < 64 * 16; t += MPTS) {
        int k = t >> 4, n = t & 15;
        float w = (n < 3) ? wr3[k * 3 + n] : 0.0f;
        __nv_bfloat16 hi, lo;
        split_w(w, hi, lo);
        sB3H[k * LDB3 + n] = hi;
        sB3L[k * LDB3 + n] = lo;
    }

    // -------- build A0 = [sh | h] (row = tid, K=32) ---------------------------
    const int p = blockIdx.x * MPTS + tid;
    const int pc = (p < N) ? p : (N - 1);
    float a0[32];
    {
        float4 v;
        v = g_h0[pc]; a0[16]=v.x; a0[17]=v.y; a0[18]=v.z; a0[19]=v.w;
        v = g_h1[pc]; a0[20]=v.x; a0[21]=v.y; a0[22]=v.z; a0[23]=v.w;
        v = g_h2[pc]; a0[24]=v.x; a0[25]=v.y; a0[26]=v.z; a0[27]=v.w;
        v = g_h3[pc]; a0[28]=v.x; a0[29]=v.y; a0[30]=v.z; a0[31]=v.w;
        float vx = __fadd_rn(__fadd_rn(gd[3 * pc + 0], 1.0f), -1.0f);
        float vy = __fadd_rn(__fadd_rn(gd[3 * pc + 1], 1.0f), -1.0f);
        float vz = __fadd_rn(__fadd_rn(gd[3 * pc + 2], 1.0f), -1.0f);
        float x2 = vx * vx, y2 = vy * vy, z2 = vz * vz;
        float xy = vx * vy, yz = vy * vz, xz = vx * vz;
        a0[0]  = 0.28209479177387814f;
        a0[1]  = -0.48860251190291987f * vy;
        a0[2]  = 0.48860251190291987f * vz;
        a0[3]  = -0.48860251190291987f * vx;
        a0[4]  = 1.0925484305920792f * xy;
        a0[5]  = -1.0925484305920792f * yz;
        a0[6]  = 0.94617469575756f * z2 - 0.31539156525252f;
        a0[7]  = -1.0925484305920792f * xz;
        a0[8]  = 0.5462742152960396f * (x2 - y2);
        a0[9]  = 0.5900435899266435f * vy * (-3.0f * x2 + y2);
        a0[10] = 2.890611442640554f * xy * vz;
        a0[11] = 0.4570457994644657f * vy * (1.0f - 5.0f * z2);
        a0[12] = 0.3731763325901154f * vz * (5.0f * z2 - 3.0f);
        a0[13] = 0.4570457994644657f * vx * (1.0f - 5.0f * z2);
        a0[14] = 1.445305721320277f * vz * (x2 - y2);
        a0[15] = 0.5900435899266435f * vx * (-x2 + 3.0f * y2);
    }
    #pragma unroll
    for (int k = 0; k < 32; k++) {
        __nv_bfloat16 hi, lo;
        split_w(a0[k], hi, lo);
        sAH[tid * LDA + k] = hi;
        sAL[tid * LDA + k] = lo;
    }
    __syncthreads();   // weights + A0 visible; warps independent from here

    // -------- layer 1: [384x32] @ W1[32x64], relu -----------------------------
    wmma_layer_relu<2, 4>(sAH, sAL, sB1H, sB1L, scr, wid, lane);
    // -------- layer 2: [384x64] @ W2[64x64], relu -----------------------------
    wmma_layer_relu<4, 4>(sAH, sAL, sB2H, sB2L, scr, wid, lane);

    // -------- layer 3: [384x64] @ W3[64x16(pad)], sigmoid, store --------------
    {
        const int m0 = wid * 32;
        wmma::fragment<wmma::matrix_a, 16, 16, 16, __nv_bfloat16, wmma::row_major> ah[2][4], al[2][4];
        #pragma unroll
        for (int ms = 0; ms < 2; ms++) {
            #pragma unroll
            for (int k = 0; k < 4; k++) {
                wmma::load_matrix_sync(ah[ms][k], sAH + (m0 + ms * 16) * LDA + k * 16, LDA);
                wmma::load_matrix_sync(al[ms][k], sAL + (m0 + ms * 16) * LDA + k * 16, LDA);
            }
        }
        wmma::fragment<wmma::matrix_b, 16, 16, 16, __nv_bfloat16, wmma::row_major> bh[4], bl[4];
        #pragma unroll
        for (int k = 0; k < 4; k++) {
            wmma::load_matrix_sync(bh[k], sB3H + k * 16 * LDB3, LDB3);
            wmma::load_matrix_sync(bl[k], sB3L + k * 16 * LDB3, LDB3);
        }
        #pragma unroll
        for (int ms = 0; ms < 2; ms++) {
            wmma::fragment<wmma::accumulator, 16, 16, 16, float> acc;
            wmma::fill_fragment(acc, 0.0f);
            #pragma unroll
            for (int k = 0; k < 4; k++) {
                wmma::mma_sync(acc, ah[ms][k], bh[k], acc);
                wmma::mma_sync(acc, ah[ms][k], bl[k], acc);
                wmma::mma_sync(acc, al[ms][k], bh[k], acc);
            }
            wmma::store_matrix_sync(scr, acc, LDS_, wmma::mem_row_major);
            __syncwarp();
            if (lane < 16) {
                const int row = blockIdx.x * MPTS + m0 + ms * 16 + lane;
                if (row < N) {
                    float r0 = scr[lane * LDS_ + 0];
                    float r1 = scr[lane * LDS_ + 1];
                    float r2 = scr[lane * LDS_ + 2];
                    out[N + 3 * row + 0] = __fdividef(1.0f, 1.0f + __expf(-r0));
                    out[N + 3 * row + 1] = __fdividef(1.0f, 1.0f + __expf(-r1));
                    out[N + 3 * row + 2] = __fdividef(1.0f, 1.0f + __expf(-r2));
                }
            }
            __syncwarp();
        }
    }
}

extern "C" void kernel_launch(void* const* d_in, const int* in_sizes, int n_in,
                              void* d_out, int out_size) {
    const float* x     = (const float*)d_in[0];
    const float* d     = (const float*)d_in[1];
    const float* table = (const float*)d_in[2];
    const float* w1    = (const float*)d_in[3];
    const float* w2    = (const float*)d_in[4];
    const float* wa1   = (const float*)d_in[5];
    const float* wa2   = (const float*)d_in[6];
    const float* wu1   = (const float*)d_in[7];
    const float* wu2   = (const float*)d_in[8];
    const float* wr1   = (const float*)d_in[9];
    const float* wr2   = (const float*)d_in[10];
    const float* wr3   = (const float*)d_in[11];
    float* out = (float*)d_out;

    int N = in_sizes[0] / 3;

    LevelP lp;
    double Bv = exp(log(2048.0 / 16.0) / 15.0);
    uint32_t mask = 0;
    for (int l = 0; l < NLEV; l++) {
        double s = 16.0 * pow(Bv, (double)l) - 1.0;
        lp.scale[l] = (float)s;
        long long r = (long long)ceil(s) + 1;
        lp.res[l] = (uint32_t)r;
        if (r * r * r <= (long long)TBL) mask |= (1u << l);
    }
    lp.dense_mask = mask;

    static int smem_set = 0;
    if (!smem_set) {
        cudaFuncSetAttribute(ngp_render_wmma,
                             cudaFuncAttributeMaxDynamicSharedMemorySize,
                             R_SMEM);
        smem_set = 1;
    }

    int eblocks = (N + 255) / 256;
    ngp_encode_kernel<<<eblocks, 128>>>(x, table, w1, w2, wa1, wa2,
                                        wu1, wu2, out, N, lp);
    int rblocks = (N + MPTS - 1) / MPTS;
    ngp_render_wmma<<<rblocks, MPTS, R_SMEM>>>(d, wr1, wr2, wr3, out, N);
}

// round 16
// speedup vs baseline: 1.2202x; 1.0112x over previous
#include <cuda_runtime.h>
#include <cuda_bf16.h>
#include <mma.h>
#include <math.h>
#include <stdint.h>

#define NLEV 16
#define TBL (1u << 19)
#define NMAX (1 << 20)

struct LevelP {
    float scale[NLEV];
    uint32_t res[NLEV];
    uint32_t dense_mask;
};

// Planar float4 scratch for enc[32] per point: 8 planes x 16 MB = 128 MB.
__device__ float4 g_e[8][NMAX];

// ---------------- grid encode for one point (enc stays in regs) -------------
__device__ __forceinline__ void grid_encode_pt(float px, float py, float pz,
                                               const float* __restrict__ table,
                                               const LevelP& lp, float* enc)
{
    #pragma unroll
    for (int l = 0; l < NLEV; l++) {
        const float s = lp.scale[l];
        const uint32_t res = lp.res[l];
        const bool dense = (lp.dense_mask >> l) & 1u;

        float posx = __fadd_rn(__fmul_rn(px, s), 0.5f);
        float posy = __fadd_rn(__fmul_rn(py, s), 0.5f);
        float posz = __fadd_rn(__fmul_rn(pz, s), 0.5f);
        float gxf = floorf(posx), gyf = floorf(posy), gzf = floorf(posz);
        float fx = posx - gxf, fy = posy - gyf, fz = posz - gzf;
        uint32_t X = (uint32_t)gxf, Y = (uint32_t)gyf, Z = (uint32_t)gzf;

        const float2* tab = (const float2*)table + (size_t)l * TBL;

        uint32_t hy0 = Y * 2654435761u;
        uint32_t hy1 = (Y + 1u) * 2654435761u;
        uint32_t hz0 = Z * 805459861u;
        uint32_t hz1 = (Z + 1u) * 805459861u;
        uint32_t dy0 = Y * res,        dy1 = (Y + 1u) * res;
        uint32_t dz0 = Z * res * res,  dz1 = (Z + 1u) * res * res;

        float wx1 = fx, wx0 = 1.0f - fx;
        float wy1 = fy, wy0 = 1.0f - fy;
        float wz1 = fz, wz0 = 1.0f - fz;

        float e0 = 0.0f, e1 = 0.0f;
        #pragma unroll
        for (int c = 0; c < 8; c++) {
            const uint32_t bi = (c >> 2) & 1, bj = (c >> 1) & 1, bk = c & 1;
            uint32_t cx = X + bi;
            uint32_t idx;
            if (dense) {
                idx = cx + (bj ? dy1 : dy0) + (bk ? dz1 : dz0);
            } else {
                idx = (cx ^ (bj ? hy1 : hy0) ^ (bk ? hz1 : hz0)) & (TBL - 1u);
            }
            float w = (bi ? wx1 : wx0) * (bj ? wy1 : wy0) * (bk ? wz1 : wz0);
            float2 f = __ldg(tab + idx);
            e0 = fmaf(f.x, w, e0);
            e1 = fmaf(f.y, w, e1);
        }
        enc[2 * l + 0] = e0;
        enc[2 * l + 1] = e1;
    }
}

// ============================ Kernel 1: pure gather encode ==================
__global__ __launch_bounds__(256, 2)
void ngp_gather_kernel(const float* __restrict__ gx,
                       const float* __restrict__ table,
                       int N, LevelP lp)
{
    int i0 = blockIdx.x * blockDim.x + threadIdx.x;
    if (i0 >= N) return;

    float px = __fmul_rn(__fadd_rn(gx[3 * i0 + 0], 1.0f), 0.5f);
    float py = __fmul_rn(__fadd_rn(gx[3 * i0 + 1], 1.0f), 0.5f);
    float pz = __fmul_rn(__fadd_rn(gx[3 * i0 + 2], 1.0f), 0.5f);

    float enc[32];
    grid_encode_pt(px, py, pz, table, lp, enc);

    #pragma unroll
    for (int q = 0; q < 8; q++)
        g_e[q][i0] = make_float4(enc[4 * q + 0], enc[4 * q + 1],
                                 enc[4 * q + 2], enc[4 * q + 3]);
}

// ============================ Kernel 2: full wmma MLP =======================
// 384 points/block, 12 warps, warp owns rows 32w..32w+31; after one staging
// __syncthreads, warps run the whole network independently (__syncwarp only).
// A-column choreography (width 72):
//   enc(0..31) -> z=relu(enc@w1)(0..63) -> h=z@w2(16..31)
//   -> za=relu(h@wa1)(32..63) -> heads [h|za]@B4 -> sigma/uncert out
//   -> sh(0..15) -> [sh|h]@wr1 relu (0..63) -> @wr2 relu (0..63) -> @wr3 rgb
// Split-bf16 (Markidis): D = hi*hi + hi*lo + lo*hi in fp32 accumulators.

#define MPTS 384
#define LDA  72
#define LDS_ 20
#define LDB_S 24        // small-B ldm (N=16 matrices)
// dynamic smem byte offsets
#define R_AH    0         // 384*72*2 = 55296
#define R_AL    55296
#define R_W1H   110592    // 32*72*2 = 4608
#define R_W1L   115200
#define R_W2H   119808    // 64*24*2 = 3072
#define R_W2L   122880
#define R_WA1H  125952    // 16*72*2 = 2304
#define R_WA1L  128256
#define R_B4H   130560    // 48*24*2 = 2304
#define R_B4L   132864
#define R_R1H   135168    // 4608
#define R_R1L   139776
#define R_R2H   144384    // 64*72*2 = 9216
#define R_R2L   153600
#define R_R3H   162816    // 3072
#define R_R3L   165888
#define R_SCR   168960    // 12 * 16*20*4 = 15360
#define R_SMEM  184320

using namespace nvcuda;

__device__ __forceinline__ void split_w(float v, __nv_bfloat16& hi, __nv_bfloat16& lo) {
    hi = __float2bfloat16(v);
    lo = __float2bfloat16(v - __bfloat162float(hi));
}
__device__ __forceinline__ uint32_t pack_bf2(__nv_bfloat16 a, __nv_bfloat16 b) {
    __nv_bfloat162 t; t.x = a; t.y = b;
    return *(uint32_t*)&t;
}

// Generic feed-forward layer: A[in_col..in_col+16K) @ B -> A[out_col..),
// optional relu, routed through per-warp scratch. Caches A frags first, so
// out may overlap in.
template <int KT, int NT, bool RELU>
__device__ __forceinline__ void wmma_ff(__nv_bfloat16* sAH, __nv_bfloat16* sAL,
                                        int in_col, int out_col,
                                        const __nv_bfloat16* sBH,
                                        const __nv_bfloat16* sBL, int ldb,
                                        float* scr, int wid, int lane)
{
    const int m0 = wid * 32;
    wmma::fragment<wmma::matrix_a, 16, 16, 16, __nv_bfloat16, wmma::row_major> ah[2][KT], al[2][KT];
    #pragma unroll
    for (int ms = 0; ms < 2; ms++)
        #pragma unroll
        for (int k = 0; k < KT; k++) {
            wmma::load_matrix_sync(ah[ms][k], sAH + (m0 + ms * 16) * LDA + in_col + k * 16, LDA);
            wmma::load_matrix_sync(al[ms][k], sAL + (m0 + ms * 16) * LDA + in_col + k * 16, LDA);
        }
    const int r  = lane & 15;
    const int ch = lane >> 4;
    #pragma unroll
    for (int nt = 0; nt < NT; nt++) {
        wmma::fragment<wmma::matrix_b, 16, 16, 16, __nv_bfloat16, wmma::row_major> bh[KT], bl[KT];
        #pragma unroll
        for (int k = 0; k < KT; k++) {
            wmma::load_matrix_sync(bh[k], sBH + k * 16 * ldb + nt * 16, ldb);
            wmma::load_matrix_sync(bl[k], sBL + k * 16 * ldb + nt * 16, ldb);
        }
        #pragma unroll
        for (int ms = 0; ms < 2; ms++) {
            wmma::fragment<wmma::accumulator, 16, 16, 16, float> acc;
            wmma::fill_fragment(acc, 0.0f);
            #pragma unroll
            for (int k = 0; k < KT; k++) {
                wmma::mma_sync(acc, ah[ms][k], bh[k], acc);
                wmma::mma_sync(acc, ah[ms][k], bl[k], acc);
                wmma::mma_sync(acc, al[ms][k], bh[k], acc);
            }
            if (RELU) {
                #pragma unroll
                for (int t = 0; t < acc.num_elements; t++)
                    acc.x[t] = fmaxf(acc.x[t], 0.0f);
            }
            wmma::store_matrix_sync(scr, acc, LDS_, wmma::mem_row_major);
            __syncwarp();
            float4 v0 = *(const float4*)&scr[r * LDS_ + ch * 8];
            float4 v1 = *(const float4*)&scr[r * LDS_ + ch * 8 + 4];
            float vv[8] = {v0.x, v0.y, v0.z, v0.w, v1.x, v1.y, v1.z, v1.w};
            uint32_t hw[4], lw[4];
            #pragma unroll
            for (int j = 0; j < 4; j++) {
                __nv_bfloat16 h0, l0, h1, l1;
                split_w(vv[2 * j + 0], h0, l0);
                split_w(vv[2 * j + 1], h1, l1);
                hw[j] = pack_bf2(h0, h1);
                lw[j] = pack_bf2(l0, l1);
            }
            const int row = m0 + ms * 16 + r;
            const int col = out_col + nt * 16 + ch * 8;
            *(uint4*)&sAH[row * LDA + col] = make_uint4(hw[0], hw[1], hw[2], hw[3]);
            *(uint4*)&sAL[row * LDA + col] = make_uint4(lw[0], lw[1], lw[2], lw[3]);
            __syncwarp();
        }
    }
}

__global__ __launch_bounds__(MPTS)
void ngp_mlp_wmma(const float* __restrict__ gd,
                  const float* __restrict__ w1,
                  const float* __restrict__ w2,
                  const float* __restrict__ wa1,
                  const float* __restrict__ wa2,
                  const float* __restrict__ wu1,
                  const float* __restrict__ wu2,
                  const float* __restrict__ wr1,
                  const float* __restrict__ wr2,
                  const float* __restrict__ wr3,
                  float* __restrict__ out,
                  int N)
{
    extern __shared__ __align__(16) char dsm[];
    __nv_bfloat16* sAH   = (__nv_bfloat16*)(dsm + R_AH);
    __nv_bfloat16* sAL   = (__nv_bfloat16*)(dsm + R_AL);
    __nv_bfloat16* sW1H  = (__nv_bfloat16*)(dsm + R_W1H);
    __nv_bfloat16* sW1L  = (__nv_bfloat16*)(dsm + R_W1L);
    __nv_bfloat16* sW2H  = (__nv_bfloat16*)(dsm + R_W2H);
    __nv_bfloat16* sW2L  = (__nv_bfloat16*)(dsm + R_W2L);
    __nv_bfloat16* sWA1H = (__nv_bfloat16*)(dsm + R_WA1H);
    __nv_bfloat16* sWA1L = (__nv_bfloat16*)(dsm + R_WA1L);
    __nv_bfloat16* sB4H  = (__nv_bfloat16*)(dsm + R_B4H);
    __nv_bfloat16* sB4L  = (__nv_bfloat16*)(dsm + R_B4L);
    __nv_bfloat16* sR1H  = (__nv_bfloat16*)(dsm + R_R1H);
    __nv_bfloat16* sR1L  = (__nv_bfloat16*)(dsm + R_R1L);
    __nv_bfloat16* sR2H  = (__nv_bfloat16*)(dsm + R_R2H);
    __nv_bfloat16* sR2L  = (__nv_bfloat16*)(dsm + R_R2L);
    __nv_bfloat16* sR3H  = (__nv_bfloat16*)(dsm + R_R3H);
    __nv_bfloat16* sR3L  = (__nv_bfloat16*)(dsm + R_R3L);

    const int tid = threadIdx.x;
    const int wid = tid >> 5;
    const int lane = tid & 31;
    float* scr = (float*)(dsm + R_SCR) + wid * (16 * LDS_);

    // -------- stage split-bf16 weights ----------------------------------------
    for (int t = tid; t < 32 * 64; t += MPTS) {          // w1 [32][64]
        int k = t >> 6, n = t & 63;
        __nv_bfloat16 hi, lo; split_w(w1[k * 64 + n], hi, lo);
        sW1H[k * LDA + n] = hi; sW1L[k * LDA + n] = lo;
    }
    for (int t = tid; t < 64 * 16; t += MPTS) {          // w2 [64][16]
        int k = t >> 4, n = t & 15;
        __nv_bfloat16 hi, lo; split_w(w2[k * 16 + n], hi, lo);
        sW2H[k * LDB_S + n] = hi; sW2L[k * LDB_S + n] = lo;
    }
    for (int t = tid; t < 16 * 32; t += MPTS) {          // wa1 [16][32]
        int k = t >> 5, n = t & 31;
        __nv_bfloat16 hi, lo; split_w(wa1[k * 32 + n], hi, lo);
        sWA1H[k * LDA + n] = hi; sWA1L[k * LDA + n] = lo;
    }
    for (int t = tid; t < 48 * 16; t += MPTS) {          // B4 [48][16]: c0=wa2(za), c1=wuf(h)
        int k = t >> 4, n = t & 15;
        float v = 0.0f;
        if (n == 0 && k >= 16) v = wa2[k - 16];
        if (n == 1 && k < 16) {
            float acc = 0.0f;
            for (int j = 0; j < 32; j++) acc = fmaf(wu1[k * 32 + j], wu2[j], acc);
            v = acc;
        }
        __nv_bfloat16 hi, lo; split_w(v, hi, lo);
        sB4H[k * LDB_S + n] = hi; sB4L[k * LDB_S + n] = lo;
    }
    for (int t = tid; t < 32 * 64; t += MPTS) {          // wr1 [32][64]
        int k = t >> 6, n = t & 63;
        __nv_bfloat16 hi, lo; split_w(wr1[k * 64 + n], hi, lo);
        sR1H[k * LDA + n] = hi; sR1L[k * LDA + n] = lo;
    }
    for (int t = tid; t < 64 * 64; t += MPTS) {          // wr2 [64][64]
        int k = t >> 6, n = t & 63;
        __nv_bfloat16 hi, lo; split_w(wr2[k * 64 + n], hi, lo);
        sR2H[k * LDA + n] = hi; sR2L[k * LDA + n] = lo;
    }
    for (int t = tid; t < 64 * 16; t += MPTS) {          // wr3 [64][3 pad 16]
        int k = t >> 4, n = t & 15;
        float v = (n < 3) ? wr3[k * 3 + n] : 0.0f;
        __nv_bfloat16 hi, lo; split_w(v, hi, lo);
        sR3H[k * LDB_S + n] = hi; sR3L[k * LDB_S + n] = lo;
    }

    // -------- stage enc -> A cols 0..31 ---------------------------------------
    const int p = blockIdx.x * MPTS + tid;
    const int pc = (p < N) ? p : (N - 1);
    #pragma unroll
    for (int q = 0; q < 8; q++) {
        float4 v = g_e[q][pc];
        __nv_bfloat16 h0, l0, h1, l1, h2, l2, h3, l3;
        split_w(v.x, h0, l0); split_w(v.y, h1, l1);
        split_w(v.z, h2, l2); split_w(v.w, h3, l3);
        *(uint2*)&sAH[tid * LDA + 4 * q] = make_uint2(pack_bf2(h0, h1), pack_bf2(h2, h3));
        *(uint2*)&sAL[tid * LDA + 4 * q] = make_uint2(pack_bf2(l0, l1), pack_bf2(l2, l3));
    }
    __syncthreads();   // weights + enc visible; warps independent from here

    // -------- z = relu(enc @ w1): cols 0..31 -> 0..63 --------------------------
    wmma_ff<2, 4, true>(sAH, sAL, 0, 0, sW1H, sW1L, LDA, scr, wid, lane);
    // -------- h = z @ w2 (no relu): cols 0..63 -> 16..31 -----------------------
    wmma_ff<4, 1, false>(sAH, sAL, 0, 16, sW2H, sW2L, LDB_S, scr, wid, lane);
    // -------- za = relu(h @ wa1): cols 16..31 -> 32..63 ------------------------
    wmma_ff<1, 2, true>(sAH, sAL, 16, 32, sWA1H, sWA1L, LDA, scr, wid, lane);

    // -------- heads: [h|za] (cols 16..63) @ B4 -> sigma/uncert -----------------
    {
        const int m0 = wid * 32;
        wmma::fragment<wmma::matrix_a, 16, 16, 16, __nv_bfloat16, wmma::row_major> ah[2][3], al[2][3];
        #pragma unroll
        for (int ms = 0; ms < 2; ms++)
            #pragma unroll
            for (int k = 0; k < 3; k++) {
                wmma::load_matrix_sync(ah[ms][k], sAH + (m0 + ms * 16) * LDA + 16 + k * 16, LDA);
                wmma::load_matrix_sync(al[ms][k], sAL + (m0 + ms * 16) * LDA + 16 + k * 16, LDA);
            }
        wmma::fragment<wmma::matrix_b, 16, 16, 16, __nv_bfloat16, wmma::row_major> bh[3], bl[3];
        #pragma unroll
        for (int k = 0; k < 3; k++) {
            wmma::load_matrix_sync(bh[k], sB4H + k * 16 * LDB_S, LDB_S);
            wmma::load_matrix_sync(bl[k], sB4L + k * 16 * LDB_S, LDB_S);
        }
        #pragma unroll
        for (int ms = 0; ms < 2; ms++) {
            wmma::fragment<wmma::accumulator, 16, 16, 16, float> acc;
            wmma::fill_fragment(acc, 0.0f);
            #pragma unroll
            for (int k = 0; k < 3; k++) {
                wmma::mma_sync(acc, ah[ms][k], bh[k], acc);
                wmma::mma_sync(acc, ah[ms][k], bl[k], acc);
                wmma::mma_sync(acc, al[ms][k], bh[k], acc);
            }
            wmma::store_matrix_sync(scr, acc, LDS_, wmma::mem_row_major);
            __syncwarp();
            if (lane < 16) {
                const int row = blockIdx.x * MPTS + m0 + ms * 16 + lane;
                if (row < N) {
                    out[row]         = __expf(scr[lane * LDS_ + 0]);
                    out[4 * N + row] = __expf(scr[lane * LDS_ + 1]);
                }
            }
            __syncwarp();
        }
    }

    // -------- sh -> cols 0..15 (own row; z[0..15] is dead) ---------------------
    {
        float vx = __fadd_rn(__fadd_rn(gd[3 * pc + 0], 1.0f), -1.0f);
        float vy = __fadd_rn(__fadd_rn(gd[3 * pc + 1], 1.0f), -1.0f);
        float vz = __fadd_rn(__fadd_rn(gd[3 * pc + 2], 1.0f), -1.0f);
        float x2 = vx * vx, y2 = vy * vy, z2 = vz * vz;
        float xy = vx * vy, yz = vy * vz, xz = vx * vz;
        float sh[16];
        sh[0]  = 0.28209479177387814f;
        sh[1]  = -0.48860251190291987f * vy;
        sh[2]  = 0.48860251190291987f * vz;
        sh[3]  = -0.48860251190291987f * vx;
        sh[4]  = 1.0925484305920792f * xy;
        sh[5]  = -1.0925484305920792f * yz;
        sh[6]  = 0.94617469575756f * z2 - 0.31539156525252f;
        sh[7]  = -1.0925484305920792f * xz;
        sh[8]  = 0.5462742152960396f * (x2 - y2);
        sh[9]  = 0.5900435899266435f * vy * (-3.0f * x2 + y2);
        sh[10] = 2.890611442640554f * xy * vz;
        sh[11] = 0.4570457994644657f * vy * (1.0f - 5.0f * z2);
        sh[12] = 0.3731763325901154f * vz * (5.0f * z2 - 3.0f);
        sh[13] = 0.4570457994644657f * vx * (1.0f - 5.0f * z2);
        sh[14] = 1.445305721320277f * vz * (x2 - y2);
        sh[15] = 0.5900435899266435f * vx * (-x2 + 3.0f * y2);
        #pragma unroll
        for (int q = 0; q < 8; q++) {
            __nv_bfloat16 h0, l0, h1, l1;
            split_w(sh[2 * q + 0], h0, l0);
            split_w(sh[2 * q + 1], h1, l1);
            *(uint32_t*)&sAH[tid * LDA + 2 * q] = pack_bf2(h0, h1);
            *(uint32_t*)&sAL[tid * LDA + 2 * q] = pack_bf2(l0, l1);
        }
        __syncwarp();
    }

    // -------- render: [sh|h](0..31) @ wr1 relu -> (0..63) ----------------------
    wmma_ff<2, 4, true>(sAH, sAL, 0, 0, sR1H, sR1L, LDA, scr, wid, lane);
    // -------- @ wr2 relu -> (0..63) --------------------------------------------
    wmma_ff<4, 4, true>(sAH, sAL, 0, 0, sR2H, sR2L, LDA, scr, wid, lane);

    // -------- @ wr3 -> rgb sigmoid ---------------------------------------------
    {
        const int m0 = wid * 32;
        wmma::fragment<wmma::matrix_a, 16, 16, 16, __nv_bfloat16, wmma::row_major> ah[2][4], al[2][4];
        #pragma unroll
        for (int ms = 0; ms < 2; ms++)
            #pragma unroll
            for (int k = 0; k < 4; k++) {
                wmma::load_matrix_sync(ah[ms][k], sAH + (m0 + ms * 16) * LDA + k * 16, LDA);
                wmma::load_matrix_sync(al[ms][k], sAL + (m0 + ms * 16) * LDA + k * 16, LDA);
            }
        wmma::fragment<wmma::matrix_b, 16, 16, 16, __nv_bfloat16, wmma::row_major> bh[4], bl[4];
        #pragma unroll
        for (int k = 0; k < 4; k++) {
            wmma::load_matrix_sync(bh[k], sR3H + k * 16 * LDB_S, LDB_S);
            wmma::load_matrix_sync(bl[k], sR3L + k * 16 * LDB_S, LDB_S);
        }
        #pragma unroll
        for (int ms = 0; ms < 2; ms++) {
            wmma::fragment<wmma::accumulator, 16, 16, 16, float> acc;
            wmma::fill_fragment(acc, 0.0f);
            #pragma unroll
            for (int k = 0; k < 4; k++) {
                wmma::mma_sync(acc, ah[ms][k], bh[k], acc);
                wmma::mma_sync(acc, ah[ms][k], bl[k], acc);
                wmma::mma_sync(acc, al[ms][k], bh[k], acc);
            }
            wmma::store_matrix_sync(scr, acc, LDS_, wmma::mem_row_major);
            __syncwarp();
            if (lane < 16) {
                const int row = blockIdx.x * MPTS + m0 + ms * 16 + lane;
                if (row < N) {
                    float r0 = scr[lane * LDS_ + 0];
                    float r1 = scr[lane * LDS_ + 1];
                    float r2 = scr[lane * LDS_ + 2];
                    out[N + 3 * row + 0] = __fdividef(1.0f, 1.0f + __expf(-r0));
                    out[N + 3 * row + 1] = __fdividef(1.0f, 1.0f + __expf(-r1));
                    out[N + 3 * row + 2] = __fdividef(1.0f, 1.0f + __expf(-r2));
                }
            }
            __syncwarp();
        }
    }
}

extern "C" void kernel_launch(void* const* d_in, const int* in_sizes, int n_in,
                              void* d_out, int out_size) {
    const float* x     = (const float*)d_in[0];
    const float* d     = (const float*)d_in[1];
    const float* table = (const float*)d_in[2];
    const float* w1    = (const float*)d_in[3];
    const float* w2    = (const float*)d_in[4];
    const float* wa1   = (const float*)d_in[5];
    const float* wa2   = (const float*)d_in[6];
    const float* wu1   = (const float*)d_in[7];
    const float* wu2   = (const float*)d_in[8];
    const float* wr1   = (const float*)d_in[9];
    const float* wr2   = (const float*)d_in[10];
    const float* wr3   = (const float*)d_in[11];
    float* out = (float*)d_out;

    int N = in_sizes[0] / 3;

    LevelP lp;
    double Bv = exp(log(2048.0 / 16.0) / 15.0);
    uint32_t mask = 0;
    for (int l = 0; l < NLEV; l++) {
        double s = 16.0 * pow(Bv, (double)l) - 1.0;
        lp.scale[l] = (float)s;
        long long r = (long long)ceil(s) + 1;
        lp.res[l] = (uint32_t)r;
        if (r * r * r <= (long long)TBL) mask |= (1u << l);
    }
    lp.dense_mask = mask;

    static int smem_set = 0;
    if (!smem_set) {
        cudaFuncSetAttribute(ngp_mlp_wmma,
                             cudaFuncAttributeMaxDynamicSharedMemorySize,
                             R_SMEM);
        smem_set = 1;
    }

    int eblocks = (N + 255) / 256;
    ngp_gather_kernel<<<eblocks, 256>>>(x, table, N, lp);
    int rblocks = (N + MPTS - 1) / MPTS;
    ngp_mlp_wmma<<<rblocks, MPTS, R_SMEM>>>(d, w1, w2, wa1, wa2, wu1, wu2,
                                            wr1, wr2, wr3, out, N);
}

// round 17
// speedup vs baseline: 1.2967x; 1.0627x over previous
#include <cuda_runtime.h>
#include <cuda_bf16.h>
#include <mma.h>
#include <math.h>
#include <stdint.h>

#define NLEV 16
#define TBL (1u << 19)
#define NMAX (1 << 20)

struct LevelP {
    float scale[NLEV];
    uint32_t res[NLEV];
    uint32_t dense_mask;
};

// Planar float4 scratch for enc[32] per point: 8 planes x 16 MB = 128 MB.
__device__ float4 g_e[8][NMAX];

// ---------------- grid encode for one point (enc stays in regs) -------------
__device__ __forceinline__ void grid_encode_pt(float px, float py, float pz,
                                               const float* __restrict__ table,
                                               const LevelP& lp, float* enc)
{
    #pragma unroll
    for (int l = 0; l < NLEV; l++) {
        const float s = lp.scale[l];
        const uint32_t res = lp.res[l];
        const bool dense = (lp.dense_mask >> l) & 1u;

        float posx = __fadd_rn(__fmul_rn(px, s), 0.5f);
        float posy = __fadd_rn(__fmul_rn(py, s), 0.5f);
        float posz = __fadd_rn(__fmul_rn(pz, s), 0.5f);
        float gxf = floorf(posx), gyf = floorf(posy), gzf = floorf(posz);
        float fx = posx - gxf, fy = posy - gyf, fz = posz - gzf;
        uint32_t X = (uint32_t)gxf, Y = (uint32_t)gyf, Z = (uint32_t)gzf;

        const float2* tab = (const float2*)table + (size_t)l * TBL;

        uint32_t hy0 = Y * 2654435761u;
        uint32_t hy1 = (Y + 1u) * 2654435761u;
        uint32_t hz0 = Z * 805459861u;
        uint32_t hz1 = (Z + 1u) * 805459861u;
        uint32_t dy0 = Y * res,        dy1 = (Y + 1u) * res;
        uint32_t dz0 = Z * res * res,  dz1 = (Z + 1u) * res * res;

        float wx1 = fx, wx0 = 1.0f - fx;
        float wy1 = fy, wy0 = 1.0f - fy;
        float wz1 = fz, wz0 = 1.0f - fz;

        float e0 = 0.0f, e1 = 0.0f;
        #pragma unroll
        for (int c = 0; c < 8; c++) {
            const uint32_t bi = (c >> 2) & 1, bj = (c >> 1) & 1, bk = c & 1;
            uint32_t cx = X + bi;
            uint32_t idx;
            if (dense) {
                idx = cx + (bj ? dy1 : dy0) + (bk ? dz1 : dz0);
            } else {
                idx = (cx ^ (bj ? hy1 : hy0) ^ (bk ? hz1 : hz0)) & (TBL - 1u);
            }
            float w = (bi ? wx1 : wx0) * (bj ? wy1 : wy0) * (bk ? wz1 : wz0);
            float2 f = __ldg(tab + idx);
            e0 = fmaf(f.x, w, e0);
            e1 = fmaf(f.y, w, e1);
        }
        enc[2 * l + 0] = e0;
        enc[2 * l + 1] = e1;
    }
}

// ============================ Kernel 1: pure gather encode ==================
__global__ __launch_bounds__(256, 2)
void ngp_gather_kernel(const float* __restrict__ gx,
                       const float* __restrict__ table,
                       int N, LevelP lp)
{
    int i0 = blockIdx.x * blockDim.x + threadIdx.x;
    if (i0 >= N) return;

    float px = __fmul_rn(__fadd_rn(gx[3 * i0 + 0], 1.0f), 0.5f);
    float py = __fmul_rn(__fadd_rn(gx[3 * i0 + 1], 1.0f), 0.5f);
    float pz = __fmul_rn(__fadd_rn(gx[3 * i0 + 2], 1.0f), 0.5f);

    float enc[32];
    grid_encode_pt(px, py, pz, table, lp, enc);

    #pragma unroll
    for (int q = 0; q < 8; q++)
        g_e[q][i0] = make_float4(enc[4 * q + 0], enc[4 * q + 1],
                                 enc[4 * q + 2], enc[4 * q + 3]);
}

// ============================ Kernel 2: full wmma MLP =======================
// 512 points/block, 16 warps, warp owns rows 32w..32w+31; after one staging
// __syncthreads, warps run the whole network independently (__syncwarp only).
// A-column choreography (width 72):
//   enc(0..31) -> z=relu(enc@w1)(0..63) -> h=z@w2(16..31)
//   -> za=relu(h@wa1)(32..63) -> heads [h|za]@B4 -> sigma/uncert out
//   -> sh(0..15) -> [sh|h]@wr1 relu (0..63) -> @wr2 relu (0..63) -> @wr3 rgb
// Split-bf16 (Markidis): D = hi*hi + hi*lo + lo*hi in fp32 accumulators.

#define MPTS 512
#define LDA  72
#define LDS_ 20
#define LDB_S 24        // small-B ldm (N=16 matrices)
// dynamic smem byte offsets
#define R_AH    0         // 512*72*2 = 73728
#define R_AL    73728
#define R_W1H   147456    // 32*72*2 = 4608
#define R_W1L   152064
#define R_W2H   156672    // 64*24*2 = 3072
#define R_W2L   159744
#define R_WA1H  162816    // 16*72*2 = 2304
#define R_WA1L  165120
#define R_B4H   167424    // 48*24*2 = 2304
#define R_B4L   169728
#define R_R1H   172032    // 4608
#define R_R1L   176640
#define R_R2H   181248    // 64*72*2 = 9216
#define R_R2L   190464
#define R_R3H   199680    // 3072
#define R_R3L   202752
#define R_SCR   205824    // 16 * 16*20*4 = 20480
#define R_SMEM  226304

using namespace nvcuda;

__device__ __forceinline__ void split_w(float v, __nv_bfloat16& hi, __nv_bfloat16& lo) {
    hi = __float2bfloat16(v);
    lo = __float2bfloat16(v - __bfloat162float(hi));
}
__device__ __forceinline__ uint32_t pack_bf2(__nv_bfloat16 a, __nv_bfloat16 b) {
    __nv_bfloat162 t; t.x = a; t.y = b;
    return *(uint32_t*)&t;
}

// Generic feed-forward layer: A[in_col..in_col+16K) @ B -> A[out_col..),
// optional relu, routed through per-warp scratch. Caches A frags first, so
// out may overlap in.
template <int KT, int NT, bool RELU>
__device__ __forceinline__ void wmma_ff(__nv_bfloat16* sAH, __nv_bfloat16* sAL,
                                        int in_col, int out_col,
                                        const __nv_bfloat16* sBH,
                                        const __nv_bfloat16* sBL, int ldb,
                                        float* scr, int wid, int lane)
{
    const int m0 = wid * 32;
    wmma::fragment<wmma::matrix_a, 16, 16, 16, __nv_bfloat16, wmma::row_major> ah[2][KT], al[2][KT];
    #pragma unroll
    for (int ms = 0; ms < 2; ms++)
        #pragma unroll
        for (int k = 0; k < KT; k++) {
            wmma::load_matrix_sync(ah[ms][k], sAH + (m0 + ms * 16) * LDA + in_col + k * 16, LDA);
            wmma::load_matrix_sync(al[ms][k], sAL + (m0 + ms * 16) * LDA + in_col + k * 16, LDA);
        }
    const int r  = lane & 15;
    const int ch = lane >> 4;
    #pragma unroll
    for (int nt = 0; nt < NT; nt++) {
        wmma::fragment<wmma::matrix_b, 16, 16, 16, __nv_bfloat16, wmma::row_major> bh[KT], bl[KT];
        #pragma unroll
        for (int k = 0; k < KT; k++) {
            wmma::load_matrix_sync(bh[k], sBH + k * 16 * ldb + nt * 16, ldb);
            wmma::load_matrix_sync(bl[k], sBL + k * 16 * ldb + nt * 16, ldb);
        }
        #pragma unroll
        for (int ms = 0; ms < 2; ms++) {
            wmma::fragment<wmma::accumulator, 16, 16, 16, float> acc;
            wmma::fill_fragment(acc, 0.0f);
            #pragma unroll
            for (int k = 0; k < KT; k++) {
                wmma::mma_sync(acc, ah[ms][k], bh[k], acc);
                wmma::mma_sync(acc, ah[ms][k], bl[k], acc);
                wmma::mma_sync(acc, al[ms][k], bh[k], acc);
            }
            if (RELU) {
                #pragma unroll
                for (int t = 0; t < acc.num_elements; t++)
                    acc.x[t] = fmaxf(acc.x[t], 0.0f);
            }
            wmma::store_matrix_sync(scr, acc, LDS_, wmma::mem_row_major);
            __syncwarp();
            float4 v0 = *(const float4*)&scr[r * LDS_ + ch * 8];
            float4 v1 = *(const float4*)&scr[r * LDS_ + ch * 8 + 4];
            float vv[8] = {v0.x, v0.y, v0.z, v0.w, v1.x, v1.y, v1.z, v1.w};
            uint32_t hw[4], lw[4];
            #pragma unroll
            for (int j = 0; j < 4; j++) {
                __nv_bfloat16 h0, l0, h1, l1;
                split_w(vv[2 * j + 0], h0, l0);
                split_w(vv[2 * j + 1], h1, l1);
                hw[j] = pack_bf2(h0, h1);
                lw[j] = pack_bf2(l0, l1);
            }
            const int row = m0 + ms * 16 + r;
            const int col = out_col + nt * 16 + ch * 8;
            *(uint4*)&sAH[row * LDA + col] = make_uint4(hw[0], hw[1], hw[2], hw[3]);
            *(uint4*)&sAL[row * LDA + col] = make_uint4(lw[0], lw[1], lw[2], lw[3]);
            __syncwarp();
        }
    }
}

__global__ __launch_bounds__(MPTS)
void ngp_mlp_wmma(const float* __restrict__ gd,
                  const float* __restrict__ w1,
                  const float* __restrict__ w2,
                  const float* __restrict__ wa1,
                  const float* __restrict__ wa2,
                  const float* __restrict__ wu1,
                  const float* __restrict__ wu2,
                  const float* __restrict__ wr1,
                  const float* __restrict__ wr2,
                  const float* __restrict__ wr3,
                  float* __restrict__ out,
                  int N)
{
    extern __shared__ __align__(16) char dsm[];
    __nv_bfloat16* sAH   = (__nv_bfloat16*)(dsm + R_AH);
    __nv_bfloat16* sAL   = (__nv_bfloat16*)(dsm + R_AL);
    __nv_bfloat16* sW1H  = (__nv_bfloat16*)(dsm + R_W1H);
    __nv_bfloat16* sW1L  = (__nv_bfloat16*)(dsm + R_W1L);
    __nv_bfloat16* sW2H  = (__nv_bfloat16*)(dsm + R_W2H);
    __nv_bfloat16* sW2L  = (__nv_bfloat16*)(dsm + R_W2L);
    __nv_bfloat16* sWA1H = (__nv_bfloat16*)(dsm + R_WA1H);
    __nv_bfloat16* sWA1L = (__nv_bfloat16*)(dsm + R_WA1L);
    __nv_bfloat16* sB4H  = (__nv_bfloat16*)(dsm + R_B4H);
    __nv_bfloat16* sB4L  = (__nv_bfloat16*)(dsm + R_B4L);
    __nv_bfloat16* sR1H  = (__nv_bfloat16*)(dsm + R_R1H);
    __nv_bfloat16* sR1L  = (__nv_bfloat16*)(dsm + R_R1L);
    __nv_bfloat16* sR2H  = (__nv_bfloat16*)(dsm + R_R2H);
    __nv_bfloat16* sR2L  = (__nv_bfloat16*)(dsm + R_R2L);
    __nv_bfloat16* sR3H  = (__nv_bfloat16*)(dsm + R_R3H);
    __nv_bfloat16* sR3L  = (__nv_bfloat16*)(dsm + R_R3L);

    const int tid = threadIdx.x;
    const int wid = tid >> 5;
    const int lane = tid & 31;
    float* scr = (float*)(dsm + R_SCR) + wid * (16 * LDS_);

    // -------- stage split-bf16 weights ----------------------------------------
    for (int t = tid; t < 32 * 64; t += MPTS) {          // w1 [32][64]
        int k = t >> 6, n = t & 63;
        __nv_bfloat16 hi, lo; split_w(w1[k * 64 + n], hi, lo);
        sW1H[k * LDA + n] = hi; sW1L[k * LDA + n] = lo;
    }
    for (int t = tid; t < 64 * 16; t += MPTS) {          // w2 [64][16]
        int k = t >> 4, n = t & 15;
        __nv_bfloat16 hi, lo; split_w(w2[k * 16 + n], hi, lo);
        sW2H[k * LDB_S + n] = hi; sW2L[k * LDB_S + n] = lo;
    }
    for (int t = tid; t < 16 * 32; t += MPTS) {          // wa1 [16][32]
        int k = t >> 5, n = t & 31;
        __nv_bfloat16 hi, lo; split_w(wa1[k * 32 + n], hi, lo);
        sWA1H[k * LDA + n] = hi; sWA1L[k * LDA + n] = lo;
    }
    for (int t = tid; t < 48 * 16; t += MPTS) {          // B4 [48][16]: c0=wa2(za), c1=wuf(h)
        int k = t >> 4, n = t & 15;
        float v = 0.0f;
        if (n == 0 && k >= 16) v = wa2[k - 16];
        if (n == 1 && k < 16) {
            float acc = 0.0f;
            for (int j = 0; j < 32; j++) acc = fmaf(wu1[k * 32 + j], wu2[j], acc);
            v = acc;
        }
        __nv_bfloat16 hi, lo; split_w(v, hi, lo);
        sB4H[k * LDB_S + n] = hi; sB4L[k * LDB_S + n] = lo;
    }
    for (int t = tid; t < 32 * 64; t += MPTS) {          // wr1 [32][64]
        int k = t >> 6, n = t & 63;
        __nv_bfloat16 hi, lo; split_w(wr1[k * 64 + n], hi, lo);
        sR1H[k * LDA + n] = hi; sR1L[k * LDA + n] = lo;
    }
    for (int t = tid; t < 64 * 64; t += MPTS) {          // wr2 [64][64]
        int k = t >> 6, n = t & 63;
        __nv_bfloat16 hi, lo; split_w(wr2[k * 64 + n], hi, lo);
        sR2H[k * LDA + n] = hi; sR2L[k * LDA + n] = lo;
    }
    for (int t = tid; t < 64 * 16; t += MPTS) {          // wr3 [64][3 pad 16]
        int k = t >> 4, n = t & 15;
        float v = (n < 3) ? wr3[k * 3 + n] : 0.0f;
        __nv_bfloat16 hi, lo; split_w(v, hi, lo);
        sR3H[k * LDB_S + n] = hi; sR3L[k * LDB_S + n] = lo;
    }

    // -------- stage enc -> A cols 0..31 ---------------------------------------
    const int p = blockIdx.x * MPTS + tid;
    const int pc = (p < N) ? p : (N - 1);
    #pragma unroll
    for (int q = 0; q < 8; q++) {
        float4 v = g_e[q][pc];
        __nv_bfloat16 h0, l0, h1, l1, h2, l2, h3, l3;
        split_w(v.x, h0, l0); split_w(v.y, h1, l1);
        split_w(v.z, h2, l2); split_w(v.w, h3, l3);
        *(uint2*)&sAH[tid * LDA + 4 * q] = make_uint2(pack_bf2(h0, h1), pack_bf2(h2, h3));
        *(uint2*)&sAL[tid * LDA + 4 * q] = make_uint2(pack_bf2(l0, l1), pack_bf2(l2, l3));
    }
    __syncthreads();   // weights + enc visible; warps independent from here

    // -------- z = relu(enc @ w1): cols 0..31 -> 0..63 --------------------------
    wmma_ff<2, 4, true>(sAH, sAL, 0, 0, sW1H, sW1L, LDA, scr, wid, lane);
    // -------- h = z @ w2 (no relu): cols 0..63 -> 16..31 -----------------------
    wmma_ff<4, 1, false>(sAH, sAL, 0, 16, sW2H, sW2L, LDB_S, scr, wid, lane);
    // -------- za = relu(h @ wa1): cols 16..31 -> 32..63 ------------------------
    wmma_ff<1, 2, true>(sAH, sAL, 16, 32, sWA1H, sWA1L, LDA, scr, wid, lane);

    // -------- heads: [h|za] (cols 16..63) @ B4 -> sigma/uncert -----------------
    {
        const int m0 = wid * 32;
        wmma::fragment<wmma::matrix_a, 16, 16, 16, __nv_bfloat16, wmma::row_major> ah[2][3], al[2][3];
        #pragma unroll
        for (int ms = 0; ms < 2; ms++)
            #pragma unroll
            for (int k = 0; k < 3; k++) {
                wmma::load_matrix_sync(ah[ms][k], sAH + (m0 + ms * 16) * LDA + 16 + k * 16, LDA);
                wmma::load_matrix_sync(al[ms][k], sAL + (m0 + ms * 16) * LDA + 16 + k * 16, LDA);
            }
        wmma::fragment<wmma::matrix_b, 16, 16, 16, __nv_bfloat16, wmma::row_major> bh[3], bl[3];
        #pragma unroll
        for (int k = 0; k < 3; k++) {
            wmma::load_matrix_sync(bh[k], sB4H + k * 16 * LDB_S, LDB_S);
            wmma::load_matrix_sync(bl[k], sB4L + k * 16 * LDB_S, LDB_S);
        }
        #pragma unroll
        for (int ms = 0; ms < 2; ms++) {
            wmma::fragment<wmma::accumulator, 16, 16, 16, float> acc;
            wmma::fill_fragment(acc, 0.0f);
            #pragma unroll
            for (int k = 0; k < 3; k++) {
                wmma::mma_sync(acc, ah[ms][k], bh[k], acc);
                wmma::mma_sync(acc, ah[ms][k], bl[k], acc);
                wmma::mma_sync(acc, al[ms][k], bh[k], acc);
            }
            wmma::store_matrix_sync(scr, acc, LDS_, wmma::mem_row_major);
            __syncwarp();
            if (lane < 16) {
                const int row = blockIdx.x * MPTS + m0 + ms * 16 + lane;
                if (row < N) {
                    out[row]         = __expf(scr[lane * LDS_ + 0]);
                    out[4 * N + row] = __expf(scr[lane * LDS_ + 1]);
                }
            }
            __syncwarp();
        }
    }

    // -------- sh -> cols 0..15 (own row; z[0..15] is dead) ---------------------
    {
        float vx = __fadd_rn(__fadd_rn(gd[3 * pc + 0], 1.0f), -1.0f);
        float vy = __fadd_rn(__fadd_rn(gd[3 * pc + 1], 1.0f), -1.0f);
        float vz = __fadd_rn(__fadd_rn(gd[3 * pc + 2], 1.0f), -1.0f);
        float x2 = vx * vx, y2 = vy * vy, z2 = vz * vz;
        float xy = vx * vy, yz = vy * vz, xz = vx * vz;
        float sh[16];
        sh[0]  = 0.28209479177387814f;
        sh[1]  = -0.48860251190291987f * vy;
        sh[2]  = 0.48860251190291987f * vz;
        sh[3]  = -0.48860251190291987f * vx;
        sh[4]  = 1.0925484305920792f * xy;
        sh[5]  = -1.0925484305920792f * yz;
        sh[6]  = 0.94617469575756f * z2 - 0.31539156525252f;
        sh[7]  = -1.0925484305920792f * xz;
        sh[8]  = 0.5462742152960396f * (x2 - y2);
        sh[9]  = 0.5900435899266435f * vy * (-3.0f * x2 + y2);
        sh[10] = 2.890611442640554f * xy * vz;
        sh[11] = 0.4570457994644657f * vy * (1.0f - 5.0f * z2);
        sh[12] = 0.3731763325901154f * vz * (5.0f * z2 - 3.0f);
        sh[13] = 0.4570457994644657f * vx * (1.0f - 5.0f * z2);
        sh[14] = 1.445305721320277f * vz * (x2 - y2);
        sh[15] = 0.5900435899266435f * vx * (-x2 + 3.0f * y2);
        #pragma unroll
        for (int q = 0; q < 8; q++) {
            __nv_bfloat16 h0, l0, h1, l1;
            split_w(sh[2 * q + 0], h0, l0);
            split_w(sh[2 * q + 1], h1, l1);
            *(uint32_t*)&sAH[tid * LDA + 2 * q] = pack_bf2(h0, h1);
            *(uint32_t*)&sAL[tid * LDA + 2 * q] = pack_bf2(l0, l1);
        }
        __syncwarp();
    }

    // -------- render: [sh|h](0..31) @ wr1 relu -> (0..63) ----------------------
    wmma_ff<2, 4, true>(sAH, sAL, 0, 0, sR1H, sR1L, LDA, scr, wid, lane);
    // -------- @ wr2 relu -> (0..63) --------------------------------------------
    wmma_ff<4, 4, true>(sAH, sAL, 0, 0, sR2H, sR2L, LDA, scr, wid, lane);

    // -------- @ wr3 -> rgb sigmoid ---------------------------------------------
    {
        const int m0 = wid * 32;
        wmma::fragment<wmma::matrix_a, 16, 16, 16, __nv_bfloat16, wmma::row_major> ah[2][4], al[2][4];
        #pragma unroll
        for (int ms = 0; ms < 2; ms++)
            #pragma unroll
            for (int k = 0; k < 4; k++) {
                wmma::load_matrix_sync(ah[ms][k], sAH + (m0 + ms * 16) * LDA + k * 16, LDA);
                wmma::load_matrix_sync(al[ms][k], sAL + (m0 + ms * 16) * LDA + k * 16, LDA);
            }
        wmma::fragment<wmma::matrix_b, 16, 16, 16, __nv_bfloat16, wmma::row_major> bh[4], bl[4];
        #pragma unroll
        for (int k = 0; k < 4; k++) {
            wmma::load_matrix_sync(bh[k], sR3H + k * 16 * LDB_S, LDB_S);
            wmma::load_matrix_sync(bl[k], sR3L + k * 16 * LDB_S, LDB_S);
        }
        #pragma unroll
        for (int ms = 0; ms < 2; ms++) {
            wmma::fragment<wmma::accumulator, 16, 16, 16, float> acc;
            wmma::fill_fragment(acc, 0.0f);
            #pragma unroll
            for (int k = 0; k < 4; k++) {
                wmma::mma_sync(acc, ah[ms][k], bh[k], acc);
                wmma::mma_sync(acc, ah[ms][k], bl[k], acc);
                wmma::mma_sync(acc, al[ms][k], bh[k], acc);
            }
            wmma::store_matrix_sync(scr, acc, LDS_, wmma::mem_row_major);
            __syncwarp();
            if (lane < 16) {
                const int row = blockIdx.x * MPTS + m0 + ms * 16 + lane;
                if (row < N) {
                    float r0 = scr[lane * LDS_ + 0];
                    float r1 = scr[lane * LDS_ + 1];
                    float r2 = scr[lane * LDS_ + 2];
                    out[N + 3 * row + 0] = __fdividef(1.0f, 1.0f + __expf(-r0));
                    out[N + 3 * row + 1] = __fdividef(1.0f, 1.0f + __expf(-r1));
                    out[N + 3 * row + 2] = __fdividef(1.0f, 1.0f + __expf(-r2));
                }
            }
            __syncwarp();
        }
    }
}

extern "C" void kernel_launch(void* const* d_in, const int* in_sizes, int n_in,
                              void* d_out, int out_size) {
    const float* x     = (const float*)d_in[0];
    const float* d     = (const float*)d_in[1];
    const float* table = (const float*)d_in[2];
    const float* w1    = (const float*)d_in[3];
    const float* w2    = (const float*)d_in[4];
    const float* wa1   = (const float*)d_in[5];
    const float* wa2   = (const float*)d_in[6];
    const float* wu1   = (const float*)d_in[7];
    const float* wu2   = (const float*)d_in[8];
    const float* wr1   = (const float*)d_in[9];
    const float* wr2   = (const float*)d_in[10];
    const float* wr3   = (const float*)d_in[11];
    float* out = (float*)d_out;

    int N = in_sizes[0] / 3;

    LevelP lp;
    double Bv = exp(log(2048.0 / 16.0) / 15.0);
    uint32_t mask = 0;
    for (int l = 0; l < NLEV; l++) {
        double s = 16.0 * pow(Bv, (double)l) - 1.0;
        lp.scale[l] = (float)s;
        long long r = (long long)ceil(s) + 1;
        lp.res[l] = (uint32_t)r;
        if (r * r * r <= (long long)TBL) mask |= (1u << l);
    }
    lp.dense_mask = mask;

    static int smem_set = 0;
    if (!smem_set) {
        cudaFuncSetAttribute(ngp_mlp_wmma,
                             cudaFuncAttributeMaxDynamicSharedMemorySize,
                             R_SMEM);
        smem_set = 1;
    }

    int eblocks = (N + 255) / 256;
    ngp_gather_kernel<<<eblocks, 256>>>(x, table, N, lp);
    int rblocks = (N + MPTS - 1) / MPTS;
    ngp_mlp_wmma<<<rblocks, MPTS, R_SMEM>>>(d, w1, w2, wa1, wa2, wu1, wu2,
                                            wr1, wr2, wr3, out, N);
}